// round 15
// baseline (speedup 1.0000x reference)
#include <cuda_runtime.h>
#include <cuda_fp16.h>
#include <cstdint>

// ---------------- problem constants ----------------
#define NNODES   20000
#define FEAT     500
#define HID      256
#define LAT      64
#define NPRED    5
#define NCLS     16
#define NODE_LEN (NNODES + NNODES * NPRED)      // 120000
#define GENF     (NPRED * FEAT)                 // 2500
#define FC1N     256
#define FC2N     2048

#define OUT_GEN_OFF ((long long)NNODES)
#define OUT_NC_OFF  ((long long)NNODES + (long long)NNODES * GENF)

// ---------------- scratch (static device globals; no allocation) ------------
__device__ float g_bufA[(size_t)NNODES * HID];
__device__ float g_bufB[(size_t)NODE_LEN * HID];
__device__ float g_z[(size_t)NNODES * LAT];
__device__ float g_c7[(size_t)NODE_LEN * NCLS];
__device__ int   g_pdeg[NNODES];
__device__ int   g_is64;
// fp16 operands
__device__ __half g_g1h[(size_t)NNODES * FC1N];
__device__ __half g_g2h[(size_t)NNODES * FC2N];
__device__ __half g_fillh[(size_t)NODE_LEN * 512];
__device__ __half g_fw3h[(size_t)NODE_LEN * HID];
__device__ __half g_fhi[(size_t)NNODES * 512];
__device__ __half g_flo[(size_t)NNODES * 512];
__device__ __half g_hhi[(size_t)NNODES * 256];
__device__ __half g_hlo[(size_t)NNODES * 256];
__device__ __half g_znh[(size_t)NNODES * 128];
__device__ __half g_wh_fc2[(size_t)2048 * 256];
__device__ __half g_wh_flat[(size_t)2560 * 2048];
__device__ __half g_wh_gc3[(size_t)256 * 512];
__device__ __half g_wh_fc1[(size_t)256 * 128];
__device__ __half g_whi_gc1[(size_t)256 * 512];
__device__ __half g_wlo_gc1[(size_t)256 * 512];
__device__ __half g_whi_gc2[(size_t)128 * 256];
__device__ __half g_wlo_gc2[(size_t)128 * 256];
// CSR scratch
__device__ int   g_cnt[NODE_LEN];
__device__ int   g_fill[NODE_LEN];
__device__ int   g_off_enc[NNODES + 1];
__device__ int   g_off_mend[NODE_LEN + 1];
__device__ int   g_ecol[700000];
__device__ float g_eval[700000];
__device__ int   g_mcol[900000];

// ---------------- helpers ----------------
__device__ __forceinline__ uint32_t smem_u32(const void* p) {
    uint32_t a;
    asm("{ .reg .u64 t; cvta.to.shared.u64 t, %1; cvt.u32.u64 %0, t; }" : "=r"(a) : "l"(p));
    return a;
}
__device__ __forceinline__ void ldsm_x4(uint32_t addr, uint32_t* r) {
    asm volatile("ldmatrix.sync.aligned.m8n8.x4.shared.b16 {%0,%1,%2,%3}, [%4];"
                 : "=r"(r[0]), "=r"(r[1]), "=r"(r[2]), "=r"(r[3]) : "r"(addr));
}
__device__ __forceinline__ void mma_f16(float* c, const uint32_t* a, uint32_t b0, uint32_t b1) {
    asm volatile(
        "mma.sync.aligned.m16n8k16.row.col.f32.f16.f16.f32 "
        "{%0,%1,%2,%3}, {%4,%5,%6,%7}, {%8,%9}, {%0,%1,%2,%3};"
        : "+f"(c[0]), "+f"(c[1]), "+f"(c[2]), "+f"(c[3])
        : "r"(a[0]), "r"(a[1]), "r"(a[2]), "r"(a[3]), "r"(b0), "r"(b1));
}
#define CP_ASYNC16(dst, src) \
    asm volatile("cp.async.cg.shared.global [%0], [%1], 16;" :: "r"(dst), "l"(src))
#define CP_COMMIT() asm volatile("cp.async.commit_group;" ::: "memory")
#define CP_WAIT(n)  asm volatile("cp.async.wait_group %0;" :: "n"(n) : "memory")

// ---------------- index dtype detection ----------------
__global__ void detect_idx_kernel(const void* adj_rows) {
    int lane = threadIdx.x;
    const long long* p = (const long long*)adj_rows;
    int bad = 0;
    for (int i = lane; i < 256; i += 32) {
        long long v = p[i];
        if (v < 0 || v >= NODE_LEN) bad = 1;
    }
    unsigned m = __ballot_sync(0xffffffffu, bad);
    if (lane == 0) g_is64 = (m == 0) ? 1 : 0;
}
__device__ __forceinline__ long long load_idx(const void* p, long long i) {
    return g_is64 ? ((const long long*)p)[i] : (long long)((const int*)p)[i];
}

// ---------------- CSR build ----------------
__global__ void enc_hist_kernel(const void* __restrict__ rows, long long nnz) {
    long long e = (long long)blockIdx.x * blockDim.x + threadIdx.x;
    if (e >= nnz) return;
    atomicAdd(&g_cnt[load_idx(rows, e)], 1);
}
__global__ void enc_fill_kernel(const void* __restrict__ rows, const void* __restrict__ cols,
                                const float* __restrict__ vals, long long nnz) {
    long long e = (long long)blockIdx.x * blockDim.x + threadIdx.x;
    if (e >= nnz) return;
    int r = (int)load_idx(rows, e);
    int pos = atomicAdd(&g_fill[r], 1);
    g_ecol[pos] = (int)load_idx(cols, e);
    g_eval[pos] = vals[e];
}
__global__ void scan_kernel(const int* __restrict__ cnt, int* __restrict__ off,
                            int* __restrict__ fill, int n) {
    __shared__ int part[1024];
    int t = threadIdx.x;
    int chunk = (n + 1023) >> 10;
    int lo = t * chunk, hi = lo + chunk;
    if (hi > n) hi = n;
    int s = 0;
    for (int i = lo; i < hi; i++) s += cnt[i];
    part[t] = s;
    __syncthreads();
    for (int d = 1; d < 1024; d <<= 1) {
        int add = (t >= d) ? part[t - d] : 0;
        __syncthreads();
        part[t] += add;
        __syncthreads();
    }
    int run = part[t] - s;
    for (int i = lo; i < hi; i++) {
        off[i] = run; fill[i] = run;
        run += cnt[i];
    }
    if (t == 1023) off[n] = part[1023];
}
__global__ void mend_hist_edges_kernel(const void* __restrict__ edges, int E) {
    int e = blockIdx.x * blockDim.x + threadIdx.x;
    if (e >= E) return;
    int lo = (int)load_idx(edges, 2LL * e);
    int hi = (int)load_idx(edges, 2LL * e + 1);
    atomicAdd(&g_cnt[lo], 1);
    atomicAdd(&g_cnt[hi], 1);
}
__global__ void mend_hist_new_kernel(const int* __restrict__ pdeg) {
    int t = blockIdx.x * blockDim.x + threadIdx.x;
    if (t >= NNODES * NPRED) return;
    int node = t / NPRED, j = t - node * NPRED;
    if (j < pdeg[node]) {
        atomicAdd(&g_cnt[node], 1);
        g_cnt[NNODES + t] = 1;
    }
}
__global__ void mend_fill_edges_kernel(const void* __restrict__ edges, int E) {
    int e = blockIdx.x * blockDim.x + threadIdx.x;
    if (e >= E) return;
    int lo = (int)load_idx(edges, 2LL * e);
    int hi = (int)load_idx(edges, 2LL * e + 1);
    int p0 = atomicAdd(&g_fill[lo], 1);
    g_mcol[p0] = hi;
    int p1 = atomicAdd(&g_fill[hi], 1);
    g_mcol[p1] = lo;
}
__global__ void mend_fill_new_kernel(const int* __restrict__ pdeg) {
    int t = blockIdx.x * blockDim.x + threadIdx.x;
    if (t >= NNODES * NPRED) return;
    int node = t / NPRED, j = t - node * NPRED;
    if (j < pdeg[node]) {
        int p0 = atomicAdd(&g_fill[node], 1);
        g_mcol[p0] = NNODES + t;
        g_mcol[g_off_mend[NNODES + t]] = node;
    }
}

// ---------------- gather SpMM (warp per row) ----------------
template <int D, bool MEND>
__global__ void spmm_gather_kernel(const int* __restrict__ off, const int* __restrict__ cols,
                                   const float* __restrict__ vals,
                                   const float* __restrict__ x, const float* __restrict__ bias,
                                   float* __restrict__ y, int nrows)
{
    int w = (int)(((long long)blockIdx.x * blockDim.x + threadIdx.x) >> 5);
    int lane = threadIdx.x & 31;
    if (w >= nrows) return;
    int e0 = off[w], e1 = off[w + 1];

    if (D == 64) {
        float a0 = 0.f, a1 = 0.f;
        const int cb = lane * 2;
        for (int e = e0; e < e1; e++) {
            long long c = cols[e];
            float2 t = *(const float2*)(x + c * 64 + cb);
            float v = vals[e];
            a0 += v * t.x; a1 += v * t.y;
        }
        float2 o;
        o.x = fmaxf(a0 + bias[cb + 0], 0.f);
        o.y = fmaxf(a1 + bias[cb + 1], 0.f);
        *(float2*)(y + (long long)w * 64 + cb) = o;
    } else {  // D == 16, MEND
        if (lane < 16) {
            float a = 0.f;
            for (int e = e0; e < e1; e++)
                a += x[(long long)cols[e] * 16 + lane];
            float inv = 1.0f / (1.0f + (float)(e1 - e0));
            float v = (a + x[(long long)w * 16 + lane]) * inv + bias[lane];
            y[(long long)w * 16 + lane] = fmaxf(v, 0.f);
        }
    }
}

// mend layer-1 gather with fp16 input x, f32 accumulate/output
__global__ void mend_gather_h_kernel(const int* __restrict__ off, const int* __restrict__ cols,
                                     const __half* __restrict__ xh, const float* __restrict__ bias,
                                     float* __restrict__ y, int nrows)
{
    int w = (int)(((long long)blockIdx.x * blockDim.x + threadIdx.x) >> 5);
    int lane = threadIdx.x & 31;
    if (w >= nrows) return;
    int e0 = off[w], e1 = off[w + 1];

    float a[8] = {0, 0, 0, 0, 0, 0, 0, 0};
    const int cb = lane * 8;
    for (int e = e0; e < e1; e++) {
        long long c = cols[e];
        const __half2* px = (const __half2*)(xh + c * 256 + cb);
        __half2 h0 = px[0], h1 = px[1], h2 = px[2], h3 = px[3];
        float2 f0 = __half22float2(h0), f1 = __half22float2(h1);
        float2 f2 = __half22float2(h2), f3 = __half22float2(h3);
        a[0] += f0.x; a[1] += f0.y; a[2] += f1.x; a[3] += f1.y;
        a[4] += f2.x; a[5] += f2.y; a[6] += f3.x; a[7] += f3.y;
    }
    float inv = 1.0f / (1.0f + (float)(e1 - e0));
    const __half2* pr = (const __half2*)(xh + (long long)w * 256 + cb);
    __half2 r0 = pr[0], r1 = pr[1], r2 = pr[2], r3 = pr[3];
    float xr[8];
    {
        float2 f0 = __half22float2(r0), f1 = __half22float2(r1);
        float2 f2 = __half22float2(r2), f3 = __half22float2(r3);
        xr[0] = f0.x; xr[1] = f0.y; xr[2] = f1.x; xr[3] = f1.y;
        xr[4] = f2.x; xr[5] = f2.y; xr[6] = f3.x; xr[7] = f3.y;
    }
    float4 o0, o1;
    o0.x = fmaxf((a[0] + xr[0]) * inv + bias[cb + 0], 0.f);
    o0.y = fmaxf((a[1] + xr[1]) * inv + bias[cb + 1], 0.f);
    o0.z = fmaxf((a[2] + xr[2]) * inv + bias[cb + 2], 0.f);
    o0.w = fmaxf((a[3] + xr[3]) * inv + bias[cb + 3], 0.f);
    o1.x = fmaxf((a[4] + xr[4]) * inv + bias[cb + 4], 0.f);
    o1.y = fmaxf((a[5] + xr[5]) * inv + bias[cb + 5], 0.f);
    o1.z = fmaxf((a[6] + xr[6]) * inv + bias[cb + 6], 0.f);
    o1.w = fmaxf((a[7] + xr[7]) * inv + bias[cb + 7], 0.f);
    *(float4*)(y + (long long)w * 256 + cb) = o0;
    *(float4*)(y + (long long)w * 256 + cb + 4) = o1;
}

// encoder gather D=256 writing split fp16 (hi, lo)
__global__ void spmm_gather_split_kernel(const int* __restrict__ off, const int* __restrict__ cols,
                                         const float* __restrict__ vals,
                                         const float* __restrict__ x, const float* __restrict__ bias,
                                         __half* __restrict__ yhi, __half* __restrict__ ylo, int nrows)
{
    int w = (int)(((long long)blockIdx.x * blockDim.x + threadIdx.x) >> 5);
    int lane = threadIdx.x & 31;
    if (w >= nrows) return;
    int e0 = off[w], e1 = off[w + 1];
    float a[8] = {0, 0, 0, 0, 0, 0, 0, 0};
    const int cb = lane * 4;
    for (int e = e0; e < e1; e++) {
        long long c = cols[e];
        float4 t0 = *(const float4*)(x + c * 256 + cb);
        float4 t1 = *(const float4*)(x + c * 256 + 128 + cb);
        float v = vals[e];
        a[0] += v * t0.x; a[1] += v * t0.y; a[2] += v * t0.z; a[3] += v * t0.w;
        a[4] += v * t1.x; a[5] += v * t1.y; a[6] += v * t1.z; a[7] += v * t1.w;
    }
#pragma unroll
    for (int g = 0; g < 2; g++) {
        int base = g * 128 + cb;
        float v0 = fmaxf(a[4 * g + 0] + bias[base + 0], 0.f);
        float v1 = fmaxf(a[4 * g + 1] + bias[base + 1], 0.f);
        float v2 = fmaxf(a[4 * g + 2] + bias[base + 2], 0.f);
        float v3 = fmaxf(a[4 * g + 3] + bias[base + 3], 0.f);
        __half h0 = __float2half_rn(v0), h1 = __float2half_rn(v1);
        __half h2 = __float2half_rn(v2), h3 = __float2half_rn(v3);
        long long o = (long long)w * 256 + base;
        *(__half2*)(yhi + o)     = __halves2half2(h0, h1);
        *(__half2*)(yhi + o + 2) = __halves2half2(h2, h3);
        *(__half2*)(ylo + o)     = __halves2half2(__float2half_rn(v0 - __half2float(h0)),
                                                  __float2half_rn(v1 - __half2float(h1)));
        *(__half2*)(ylo + o + 2) = __halves2half2(__float2half_rn(v2 - __half2float(h2)),
                                                  __float2half_rn(v3 - __half2float(h3)));
    }
}

// ---------------- weight transpose -> half ----------------
__global__ void transpose_half_kernel(const float* __restrict__ W, __half* __restrict__ WT,
                                      int K, int N, int Kpad, int Npad) {
    __shared__ float tile[32][33];
    int kb = blockIdx.x * 32, nb = blockIdx.y * 32;
    int tx = threadIdx.x, ty = threadIdx.y;   // 32 x 8
#pragma unroll
    for (int i = 0; i < 4; i++) {
        int k = kb + ty + i * 8, n = nb + tx;
        tile[ty + i * 8][tx] = (k < K && n < N) ? W[(long long)k * N + n] : 0.0f;
    }
    __syncthreads();
#pragma unroll
    for (int i = 0; i < 4; i++) {
        int n = nb + ty + i * 8, k = kb + tx;
        if (n < Npad && k < Kpad)
            WT[(long long)n * Kpad + k] = __float2half_rn(tile[tx][ty + i * 8]);
    }
}
__global__ void transpose_half_split_kernel(const float* __restrict__ W,
                                            __half* __restrict__ WThi, __half* __restrict__ WTlo,
                                            int K, int N, int Kpad, int Npad) {
    __shared__ float tile[32][33];
    int kb = blockIdx.x * 32, nb = blockIdx.y * 32;
    int tx = threadIdx.x, ty = threadIdx.y;
#pragma unroll
    for (int i = 0; i < 4; i++) {
        int k = kb + ty + i * 8, n = nb + tx;
        tile[ty + i * 8][tx] = (k < K && n < N) ? W[(long long)k * N + n] : 0.0f;
    }
    __syncthreads();
#pragma unroll
    for (int i = 0; i < 4; i++) {
        int n = nb + ty + i * 8, k = kb + tx;
        if (n < Npad && k < Kpad) {
            float v = tile[tx][ty + i * 8];
            __half h = __float2half_rn(v);
            WThi[(long long)n * Kpad + k] = h;
            WTlo[(long long)n * Kpad + k] = __float2half_rn(v - __half2float(h));
        }
    }
}
__global__ void feat_prep_kernel(const float* __restrict__ feat,
                                 __half* __restrict__ fhi, __half* __restrict__ flo,
                                 __half* __restrict__ fillh) {
    long long i = (long long)blockIdx.x * blockDim.x + threadIdx.x;
    if (i >= (long long)NNODES * 512) return;
    int r = (int)(i >> 9), c = (int)(i & 511);
    float v = (c < FEAT) ? feat[(long long)r * FEAT + c] : 0.0f;
    __half h = __float2half_rn(v);
    fhi[i] = h;
    flo[i] = __float2half_rn(v - __half2float(h));
    fillh[i] = h;
}
__global__ void add_half_pad_kernel(__half* __restrict__ o, const float* __restrict__ a,
                                    const float* __restrict__ b)
{
    long long i = (long long)blockIdx.x * blockDim.x + threadIdx.x;
    if (i >= (long long)NNODES * 128) return;
    int r = (int)(i >> 7), c = (int)(i & 127);
    o[i] = (c < LAT) ? __float2half_rn(a[(long long)r * LAT + c] + b[(long long)r * LAT + c])
                     : __half(0.0f);
}

// ---------------- fp16 mma GEMM (128x128) ------------------
#define HSTAGES 4
#define H_STRIDE_B 80
#define H_MAT_BYTES (128 * H_STRIDE_B)          // 10240
#define H_STAGE_BYTES (2 * H_MAT_BYTES)         // 20480
#define H_SMEM_TOTAL (HSTAGES * H_STAGE_BYTES)  // 81920

template <int EPI, int OUT>
__global__ void __launch_bounds__(256, 2) hmma_gemm_kernel(
    const __half* __restrict__ A, const __half* __restrict__ BT,
    const float* __restrict__ bias,
    float* __restrict__ C, __half* __restrict__ Ch,
    int M, int N, int K, int Kpad)
{
    extern __shared__ char smem[];
    const uint32_t sbase = smem_u32(smem);
    const int tid = threadIdx.x;
    const int wid = tid >> 5, lane = tid & 31;
    const int gid = lane >> 2, tig = lane & 3;
    const int warp_m = wid & 3, warp_n = wid >> 2;
    const int m0 = blockIdx.y * 128, n0 = blockIdx.x * 128;

    const int crow = tid >> 1;
    const int cboff = (tid & 1) * 32;

    const __half* aptr;
    {
        int r = m0 + crow;
        int rr = (r < M) ? r : (M - 1);
        aptr = A + (long long)rr * K;
    }
    const __half* bptr = BT + (long long)(n0 + crow) * Kpad;

    const uint32_t sA_wr = sbase + (uint32_t)crow * H_STRIDE_B + (uint32_t)cboff;
    const uint32_t sB_wr = sA_wr + H_MAT_BYTES;

    const int nChunks = K >> 5;

    auto issue = [&](int chunk) {
        int s = chunk & (HSTAGES - 1);
        uint32_t da = sA_wr + (uint32_t)s * H_STAGE_BYTES;
        uint32_t db = sB_wr + (uint32_t)s * H_STAGE_BYTES;
        const char* ga = (const char*)aptr + chunk * 64 + cboff;
        const char* gb = (const char*)bptr + chunk * 64 + cboff;
        CP_ASYNC16(da, ga); CP_ASYNC16(da + 16, ga + 16);
        CP_ASYNC16(db, gb); CP_ASYNC16(db + 16, gb + 16);
        CP_COMMIT();
    };

    float acc[2][8][4];
#pragma unroll
    for (int f = 0; f < 2; f++)
#pragma unroll
        for (int j = 0; j < 8; j++)
#pragma unroll
            for (int q = 0; q < 4; q++) acc[f][j][q] = 0.0f;

    for (int s = 0; s < HSTAGES - 1; s++) issue(s);

    uint32_t a_off[2];
#pragma unroll
    for (int f = 0; f < 2; f++) {
        uint32_t row = (uint32_t)(warp_m * 32 + f * 16 + (lane & 15));
        uint32_t colb = (uint32_t)((lane >> 4) << 4);
        a_off[f] = row * H_STRIDE_B + colb;
    }
    uint32_t b_off[4];
#pragma unroll
    for (int jp = 0; jp < 4; jp++) {
        uint32_t row = (uint32_t)(warp_n * 64 + jp * 16 + ((lane >> 4) << 3) + (lane & 7));
        uint32_t colb = (uint32_t)(((lane >> 3) & 1) << 4);
        b_off[jp] = row * H_STRIDE_B + colb;
    }

    CP_WAIT(HSTAGES - 2);
    __syncthreads();

    for (int i = 0; i < nChunks; i++) {
        uint32_t sA = sbase + (uint32_t)(i & (HSTAGES - 1)) * H_STAGE_BYTES;
        uint32_t sB = sA + H_MAT_BYTES;
#pragma unroll
        for (int kk = 0; kk < 2; kk++) {
            uint32_t afr[2][4];
            ldsm_x4(sA + a_off[0] + kk * 32, afr[0]);
            ldsm_x4(sA + a_off[1] + kk * 32, afr[1]);
#pragma unroll
            for (int jp = 0; jp < 4; jp++) {
                uint32_t br[4];
                ldsm_x4(sB + b_off[jp] + kk * 32, br);
                mma_f16(acc[0][2 * jp + 0], afr[0], br[0], br[1]);
                mma_f16(acc[1][2 * jp + 0], afr[1], br[0], br[1]);
                mma_f16(acc[0][2 * jp + 1], afr[0], br[2], br[3]);
                mma_f16(acc[1][2 * jp + 1], afr[1], br[2], br[3]);
            }
        }
        if (i + HSTAGES - 1 < nChunks) issue(i + HSTAGES - 1);
        else CP_COMMIT();
        CP_WAIT(HSTAGES - 2);
        __syncthreads();
    }

#pragma unroll
    for (int f = 0; f < 2; f++) {
#pragma unroll
        for (int rr = 0; rr < 2; rr++) {
            int r = m0 + warp_m * 32 + f * 16 + rr * 8 + gid;
            if (r >= M) continue;
#pragma unroll
            for (int j = 0; j < 8; j++) {
                int c = n0 + warp_n * 64 + j * 8 + tig * 2;
                if (c >= N) continue;
                float v0 = acc[f][j][rr * 2 + 0], v1 = acc[f][j][rr * 2 + 1];
                if (EPI >= 1) { v0 += bias[c]; v1 += bias[c + 1]; }
                if (EPI == 1) { v0 = fmaxf(v0, 0.f); v1 = fmaxf(v1, 0.f); }
                if (EPI == 2) { v0 = tanhf(v0); v1 = tanhf(v1); }
                if (OUT == 0) {
                    *(float2*)(C + (long long)r * N + c) = make_float2(v0, v1);
                } else if (OUT == 1) {
                    *(__half2*)(Ch + (long long)r * N + c) = __floats2half2_rn(v0, v1);
                } else {
                    *(float2*)(C + (long long)r * N + c) = make_float2(v0, v1);
                    int j5 = c / FEAT, cc = c - j5 * FEAT;
                    *(__half2*)(Ch + ((size_t)(NNODES + r * NPRED + j5) * 512 + cc)) =
                        __floats2half2_rn(v0, v1);
                }
            }
        }
    }
}

// ---------------- wide fp16 mma GEMM (128m x 256n, 1 CTA/SM) ---------------
// 8 warps = 2m x 4n; warp tile 64x64. Per-k16: 8 LDSM : 32 MMA.
#define W_A_BYTES (128 * H_STRIDE_B)            // 10240
#define W_B_BYTES (256 * H_STRIDE_B)            // 20480
#define W_STAGE_BYTES (W_A_BYTES + W_B_BYTES)   // 30720
#define W_SMEM_TOTAL (HSTAGES * W_STAGE_BYTES)  // 122880

template <int EPI, int OUT>
__global__ void __launch_bounds__(256, 1) hmma_gemm_wide_kernel(
    const __half* __restrict__ A, const __half* __restrict__ BT,
    const float* __restrict__ bias,
    float* __restrict__ C, __half* __restrict__ Ch,
    int M, int N, int K, int Kpad)
{
    extern __shared__ char smem[];
    const uint32_t sbase = smem_u32(smem);
    const int tid = threadIdx.x;
    const int wid = tid >> 5, lane = tid & 31;
    const int gid = lane >> 2, tig = lane & 3;
    const int warp_m = wid & 1, warp_n = wid >> 1;
    const int m0 = blockIdx.y * 128, n0 = blockIdx.x * 256;

    // staging: A rows via thread pairs; B one row per thread (64B)
    const int arow = tid >> 1;
    const int aoff = (tid & 1) * 32;
    const __half* aptr;
    {
        int r = m0 + arow;
        int rr = (r < M) ? r : (M - 1);
        aptr = A + (long long)rr * K;
    }
    const __half* bptr = BT + (long long)(n0 + tid) * Kpad;

    const uint32_t sA_wr = sbase + (uint32_t)arow * H_STRIDE_B + (uint32_t)aoff;
    const uint32_t sB_wr = sbase + W_A_BYTES + (uint32_t)tid * H_STRIDE_B;

    const int nChunks = K >> 5;

    auto issue = [&](int chunk) {
        int s = chunk & (HSTAGES - 1);
        uint32_t da = sA_wr + (uint32_t)s * W_STAGE_BYTES;
        uint32_t db = sB_wr + (uint32_t)s * W_STAGE_BYTES;
        const char* ga = (const char*)aptr + chunk * 64 + aoff;
        const char* gb = (const char*)bptr + chunk * 64;
        CP_ASYNC16(da, ga); CP_ASYNC16(da + 16, ga + 16);
        CP_ASYNC16(db, gb); CP_ASYNC16(db + 16, gb + 16);
        CP_ASYNC16(db + 32, gb + 32); CP_ASYNC16(db + 48, gb + 48);
        CP_COMMIT();
    };

    float acc[4][8][4];
#pragma unroll
    for (int f = 0; f < 4; f++)
#pragma unroll
        for (int j = 0; j < 8; j++)
#pragma unroll
            for (int q = 0; q < 4; q++) acc[f][j][q] = 0.0f;

    for (int s = 0; s < HSTAGES - 1; s++) issue(s);

    uint32_t a_off[4];
#pragma unroll
    for (int f = 0; f < 4; f++) {
        uint32_t row = (uint32_t)(warp_m * 64 + f * 16 + (lane & 15));
        uint32_t colb = (uint32_t)((lane >> 4) << 4);
        a_off[f] = row * H_STRIDE_B + colb;
    }
    uint32_t b_off[4];
#pragma unroll
    for (int jp = 0; jp < 4; jp++) {
        uint32_t row = (uint32_t)(warp_n * 64 + jp * 16 + ((lane >> 4) << 3) + (lane & 7));
        uint32_t colb = (uint32_t)(((lane >> 3) & 1) << 4);
        b_off[jp] = W_A_BYTES + row * H_STRIDE_B + colb;
    }

    CP_WAIT(HSTAGES - 2);
    __syncthreads();

    for (int i = 0; i < nChunks; i++) {
        uint32_t sS = sbase + (uint32_t)(i & (HSTAGES - 1)) * W_STAGE_BYTES;
#pragma unroll
        for (int kk = 0; kk < 2; kk++) {
            uint32_t afr[4][4];
            ldsm_x4(sS + a_off[0] + kk * 32, afr[0]);
            ldsm_x4(sS + a_off[1] + kk * 32, afr[1]);
            ldsm_x4(sS + a_off[2] + kk * 32, afr[2]);
            ldsm_x4(sS + a_off[3] + kk * 32, afr[3]);
#pragma unroll
            for (int jp = 0; jp < 4; jp++) {
                uint32_t br[4];
                ldsm_x4(sS + b_off[jp] + kk * 32, br);
#pragma unroll
                for (int f = 0; f < 4; f++) {
                    mma_f16(acc[f][2 * jp + 0], afr[f], br[0], br[1]);
                    mma_f16(acc[f][2 * jp + 1], afr[f], br[2], br[3]);
                }
            }
        }
        if (i + HSTAGES - 1 < nChunks) issue(i + HSTAGES - 1);
        else CP_COMMIT();
        CP_WAIT(HSTAGES - 2);
        __syncthreads();
    }

#pragma unroll
    for (int f = 0; f < 4; f++) {
#pragma unroll
        for (int rr = 0; rr < 2; rr++) {
            int r = m0 + warp_m * 64 + f * 16 + rr * 8 + gid;
            if (r >= M) continue;
#pragma unroll
            for (int j = 0; j < 8; j++) {
                int c = n0 + warp_n * 64 + j * 8 + tig * 2;
                if (c >= N) continue;
                float v0 = acc[f][j][rr * 2 + 0], v1 = acc[f][j][rr * 2 + 1];
                if (EPI >= 1) { v0 += bias[c]; v1 += bias[c + 1]; }
                if (EPI == 1) { v0 = fmaxf(v0, 0.f); v1 = fmaxf(v1, 0.f); }
                if (EPI == 2) { v0 = tanhf(v0); v1 = tanhf(v1); }
                if (OUT == 0) {
                    *(float2*)(C + (long long)r * N + c) = make_float2(v0, v1);
                } else if (OUT == 1) {
                    *(__half2*)(Ch + (long long)r * N + c) = __floats2half2_rn(v0, v1);
                } else {
                    *(float2*)(C + (long long)r * N + c) = make_float2(v0, v1);
                    int j5 = c / FEAT, cc = c - j5 * FEAT;
                    *(__half2*)(Ch + ((size_t)(NNODES + r * NPRED + j5) * 512 + cc)) =
                        __floats2half2_rn(v0, v1);
                }
            }
        }
    }
}

// ---------------- triple-pass split-3 GEMM: C = A0@B0 + A1@B1 + A2@B2 ------
__global__ void __launch_bounds__(256, 2) hmma_gemm3_kernel(
    const __half* __restrict__ A0, const __half* __restrict__ A1, const __half* __restrict__ A2,
    const __half* __restrict__ B0, const __half* __restrict__ B1, const __half* __restrict__ B2,
    float* __restrict__ C, int M, int N, int K, int Kpad)
{
    extern __shared__ char smem[];
    const uint32_t sbase = smem_u32(smem);
    const int tid = threadIdx.x;
    const int wid = tid >> 5, lane = tid & 31;
    const int gid = lane >> 2, tig = lane & 3;
    const int warp_m = wid & 3, warp_n = wid >> 2;
    const int m0 = blockIdx.y * 128, n0 = blockIdx.x * 128;

    const int crow = tid >> 1;
    const int cboff = (tid & 1) * 32;

    int rr = (m0 + crow < M) ? (m0 + crow) : (M - 1);
    const __half* ap0 = A0 + (long long)rr * K;
    const __half* ap1 = A1 + (long long)rr * K;
    const __half* ap2 = A2 + (long long)rr * K;
    const __half* bp0 = B0 + (long long)(n0 + crow) * Kpad;
    const __half* bp1 = B1 + (long long)(n0 + crow) * Kpad;
    const __half* bp2 = B2 + (long long)(n0 + crow) * Kpad;

    const uint32_t sA_wr = sbase + (uint32_t)crow * H_STRIDE_B + (uint32_t)cboff;
    const uint32_t sB_wr = sA_wr + H_MAT_BYTES;

    const int nChunks = K >> 5;
    const int total = 3 * nChunks;

    auto issue = [&](int t) {
        int pass = t / nChunks;
        int local = t - pass * nChunks;
        const __half* ga = (pass == 0) ? ap0 : (pass == 1) ? ap1 : ap2;
        const __half* gb = (pass == 0) ? bp0 : (pass == 1) ? bp1 : bp2;
        int s = t & (HSTAGES - 1);
        uint32_t da = sA_wr + (uint32_t)s * H_STAGE_BYTES;
        uint32_t db = sB_wr + (uint32_t)s * H_STAGE_BYTES;
        const char* pa = (const char*)ga + local * 64 + cboff;
        const char* pb = (const char*)gb + local * 64 + cboff;
        CP_ASYNC16(da, pa); CP_ASYNC16(da + 16, pa + 16);
        CP_ASYNC16(db, pb); CP_ASYNC16(db + 16, pb + 16);
        CP_COMMIT();
    };

    float acc[2][8][4];
#pragma unroll
    for (int f = 0; f < 2; f++)
#pragma unroll
        for (int j = 0; j < 8; j++)
#pragma unroll
            for (int q = 0; q < 4; q++) acc[f][j][q] = 0.0f;

    for (int s = 0; s < HSTAGES - 1; s++) issue(s);

    uint32_t a_off[2];
#pragma unroll
    for (int f = 0; f < 2; f++) {
        uint32_t row = (uint32_t)(warp_m * 32 + f * 16 + (lane & 15));
        uint32_t colb = (uint32_t)((lane >> 4) << 4);
        a_off[f] = row * H_STRIDE_B + colb;
    }
    uint32_t b_off[4];
#pragma unroll
    for (int jp = 0; jp < 4; jp++) {
        uint32_t row = (uint32_t)(warp_n * 64 + jp * 16 + ((lane >> 4) << 3) + (lane & 7));
        uint32_t colb = (uint32_t)(((lane >> 3) & 1) << 4);
        b_off[jp] = row * H_STRIDE_B + colb;
    }

    CP_WAIT(HSTAGES - 2);
    __syncthreads();

    for (int i = 0; i < total; i++) {
        uint32_t sA = sbase + (uint32_t)(i & (HSTAGES - 1)) * H_STAGE_BYTES;
        uint32_t sB = sA + H_MAT_BYTES;
#pragma unroll
        for (int kk = 0; kk < 2; kk++) {
            uint32_t afr[2][4];
            ldsm_x4(sA + a_off[0] + kk * 32, afr[0]);
            ldsm_x4(sA + a_off[1] + kk * 32, afr[1]);
#pragma unroll
            for (int jp = 0; jp < 4; jp++) {
                uint32_t br[4];
                ldsm_x4(sB + b_off[jp] + kk * 32, br);
                mma_f16(acc[0][2 * jp + 0], afr[0], br[0], br[1]);
                mma_f16(acc[1][2 * jp + 0], afr[1], br[0], br[1]);
                mma_f16(acc[0][2 * jp + 1], afr[0], br[2], br[3]);
                mma_f16(acc[1][2 * jp + 1], afr[1], br[2], br[3]);
            }
        }
        if (i + HSTAGES - 1 < total) issue(i + HSTAGES - 1);
        else CP_COMMIT();
        CP_WAIT(HSTAGES - 2);
        __syncthreads();
    }

#pragma unroll
    for (int f = 0; f < 2; f++) {
#pragma unroll
        for (int rr2 = 0; rr2 < 2; rr2++) {
            int r = m0 + warp_m * 32 + f * 16 + rr2 * 8 + gid;
            if (r >= M) continue;
#pragma unroll
            for (int j = 0; j < 8; j++) {
                int c = n0 + warp_n * 64 + j * 8 + tig * 2;
                if (c >= N) continue;
                *(float2*)(C + (long long)r * N + c) =
                    make_float2(acc[f][j][rr2 * 2 + 0], acc[f][j][rr2 * 2 + 1]);
            }
        }
    }
}

// ---------------- skinny GEMM for gc4 ----------------
__global__ void skinny16_kernel(const float* __restrict__ X, const float* __restrict__ W,
                                float* __restrict__ C, int M)
{
    __shared__ float Ws[256 * 16];
    int tid = threadIdx.x;   // 128
    for (int i = tid; i < 256 * 16; i += 128) Ws[i] = W[i];
    __syncthreads();
    int r = blockIdx.x * 128 + tid;
    if (r >= M) return;
    const float* x = X + (long long)r * 256;
    float acc[16];
#pragma unroll
    for (int q = 0; q < 16; q++) acc[q] = 0.0f;
    for (int k = 0; k < 256; k += 4) {
        float4 a = *(const float4*)(x + k);
#pragma unroll
        for (int q = 0; q < 16; q++)
            acc[q] += a.x * Ws[(k + 0) * 16 + q] + a.y * Ws[(k + 1) * 16 + q]
                    + a.z * Ws[(k + 2) * 16 + q] + a.w * Ws[(k + 3) * 16 + q];
    }
    float* co = C + (long long)r * 16;
#pragma unroll
    for (int q = 0; q < 16; q += 4)
        *(float4*)(co + q) = make_float4(acc[q], acc[q + 1], acc[q + 2], acc[q + 3]);
}

// ---------------- misc ----------------
__global__ void degree_kernel(const float* __restrict__ z, const float* __restrict__ Wr,
                              const float* __restrict__ br, float* __restrict__ deg_out,
                              int* __restrict__ pdeg, int n)
{
    int r = blockIdx.x * (blockDim.x >> 5) + (threadIdx.x >> 5);
    int lane = threadIdx.x & 31;
    if (r >= n) return;
    float s = z[(long long)r * LAT + lane] * Wr[lane]
            + z[(long long)r * LAT + 32 + lane] * Wr[32 + lane];
#pragma unroll
    for (int o = 16; o; o >>= 1) s += __shfl_xor_sync(0xffffffffu, s, o);
    if (lane == 0) {
        float d = fmaxf(s + br[0], 0.0f);
        deg_out[r] = d;
        int pi = (int)d;
        if (pi > NPRED) pi = NPRED;
        pdeg[r] = pi;
    }
}

// ---------------- host ----------------
static inline int cdiv(long long a, long long b) { return (int)((a + b - 1) / b); }

extern "C" void kernel_launch(void* const* d_in, const int* in_sizes, int n_in,
                              void* d_out, int out_size)
{
    const float* feat     = (const float*)d_in[0];
    const void*  edges    = d_in[1];
    const void*  adj_rows = d_in[2];
    const void*  adj_cols = d_in[3];
    const float* adj_vals = (const float*)d_in[4];
    const float* noise    = (const float*)d_in[5];
    const float* W_gc1 = (const float*)d_in[6];   const float* b_gc1 = (const float*)d_in[7];
    const float* W_gc2 = (const float*)d_in[8];   const float* b_gc2 = (const float*)d_in[9];
    const float* W_reg = (const float*)d_in[10];  const float* b_reg = (const float*)d_in[11];
    const float* W_fc1 = (const float*)d_in[12];  const float* b_fc1 = (const float*)d_in[13];
    const float* W_fc2 = (const float*)d_in[14];  const float* b_fc2 = (const float*)d_in[15];
    const float* W_flat = (const float*)d_in[16]; const float* b_flat = (const float*)d_in[17];
    const float* W_gc3 = (const float*)d_in[18];  const float* b_gc3 = (const float*)d_in[19];
    const float* W_gc4 = (const float*)d_in[20];  const float* b_gc4 = (const float*)d_in[21];

    float* out = (float*)d_out;
    float* out_deg = out;
    float* out_gen = out + OUT_GEN_OFF;
    float* out_nc  = out + OUT_NC_OFF;

    const long long nnz_adj = in_sizes[2];
    const int E = in_sizes[1] / 2;

    void* p;
    float *bufA, *bufB, *z, *c7;
    __half *g1h, *g2h, *fillh, *fw3h, *fhi, *flo, *hhi, *hlo, *znh;
    __half *wh_fc2, *wh_flat, *wh_gc3, *wh_fc1, *whi_gc1, *wlo_gc1, *whi_gc2, *wlo_gc2;
    int *pdeg, *cnt, *fill, *off_enc, *off_mend, *ecol, *mcol;
    float *eval;
    cudaGetSymbolAddress(&p, g_bufA);  bufA  = (float*)p;
    cudaGetSymbolAddress(&p, g_bufB);  bufB  = (float*)p;
    cudaGetSymbolAddress(&p, g_z);     z     = (float*)p;
    cudaGetSymbolAddress(&p, g_c7);    c7    = (float*)p;
    cudaGetSymbolAddress(&p, g_pdeg);  pdeg  = (int*)p;
    cudaGetSymbolAddress(&p, g_cnt);   cnt   = (int*)p;
    cudaGetSymbolAddress(&p, g_fill);  fill  = (int*)p;
    cudaGetSymbolAddress(&p, g_off_enc);  off_enc  = (int*)p;
    cudaGetSymbolAddress(&p, g_off_mend); off_mend = (int*)p;
    cudaGetSymbolAddress(&p, g_ecol);  ecol  = (int*)p;
    cudaGetSymbolAddress(&p, g_eval);  eval  = (float*)p;
    cudaGetSymbolAddress(&p, g_mcol);  mcol  = (int*)p;
    cudaGetSymbolAddress(&p, g_g1h);   g1h   = (__half*)p;
    cudaGetSymbolAddress(&p, g_g2h);   g2h   = (__half*)p;
    cudaGetSymbolAddress(&p, g_fillh); fillh = (__half*)p;
    cudaGetSymbolAddress(&p, g_fw3h);  fw3h  = (__half*)p;
    cudaGetSymbolAddress(&p, g_fhi);   fhi   = (__half*)p;
    cudaGetSymbolAddress(&p, g_flo);   flo   = (__half*)p;
    cudaGetSymbolAddress(&p, g_hhi);   hhi   = (__half*)p;
    cudaGetSymbolAddress(&p, g_hlo);   hlo   = (__half*)p;
    cudaGetSymbolAddress(&p, g_znh);   znh   = (__half*)p;
    cudaGetSymbolAddress(&p, g_wh_fc2);  wh_fc2  = (__half*)p;
    cudaGetSymbolAddress(&p, g_wh_flat); wh_flat = (__half*)p;
    cudaGetSymbolAddress(&p, g_wh_gc3);  wh_gc3  = (__half*)p;
    cudaGetSymbolAddress(&p, g_wh_fc1);  wh_fc1  = (__half*)p;
    cudaGetSymbolAddress(&p, g_whi_gc1); whi_gc1 = (__half*)p;
    cudaGetSymbolAddress(&p, g_wlo_gc1); wlo_gc1 = (__half*)p;
    cudaGetSymbolAddress(&p, g_whi_gc2); whi_gc2 = (__half*)p;
    cudaGetSymbolAddress(&p, g_wlo_gc2); wlo_gc2 = (__half*)p;

    cudaFuncSetAttribute((const void*)hmma_gemm_kernel<0, 1>,
                         cudaFuncAttributeMaxDynamicSharedMemorySize, H_SMEM_TOTAL);
    cudaFuncSetAttribute((const void*)hmma_gemm_kernel<1, 1>,
                         cudaFuncAttributeMaxDynamicSharedMemorySize, H_SMEM_TOTAL);
    cudaFuncSetAttribute((const void*)hmma_gemm_wide_kernel<2, 2>,
                         cudaFuncAttributeMaxDynamicSharedMemorySize, W_SMEM_TOTAL);
    cudaFuncSetAttribute((const void*)hmma_gemm3_kernel,
                         cudaFuncAttributeMaxDynamicSharedMemorySize, H_SMEM_TOTAL);

    const int TB = 256;
    dim3 tblk(32, 8);

    // 0) prep
    detect_idx_kernel<<<1, 32>>>(adj_rows);
    transpose_half_kernel<<<dim3(cdiv(256, 32), cdiv(2048, 32)), tblk>>>(W_fc2, wh_fc2, 256, 2048, 256, 2048);
    transpose_half_kernel<<<dim3(cdiv(2048, 32), cdiv(2560, 32)), tblk>>>(W_flat, wh_flat, 2048, 2500, 2048, 2560);
    transpose_half_kernel<<<dim3(cdiv(512, 32), cdiv(256, 32)), tblk>>>(W_gc3, wh_gc3, 500, 256, 512, 256);
    transpose_half_kernel<<<dim3(cdiv(128, 32), cdiv(256, 32)), tblk>>>(W_fc1, wh_fc1, 64, 256, 128, 256);
    transpose_half_split_kernel<<<dim3(cdiv(512, 32), cdiv(256, 32)), tblk>>>(W_gc1, whi_gc1, wlo_gc1, 500, 256, 512, 256);
    transpose_half_split_kernel<<<dim3(cdiv(256, 32), cdiv(128, 32)), tblk>>>(W_gc2, whi_gc2, wlo_gc2, 256, 64, 256, 128);
    feat_prep_kernel<<<cdiv((long long)NNODES * 512, TB), TB>>>(feat, fhi, flo, fillh);

    // 0b) encoder CSR build
    cudaMemsetAsync(cnt, 0, NNODES * sizeof(int));
    enc_hist_kernel<<<cdiv(nnz_adj, TB), TB>>>(adj_rows, nnz_adj);
    scan_kernel<<<1, 1024>>>(cnt, off_enc, fill, NNODES);
    enc_fill_kernel<<<cdiv(nnz_adj, TB), TB>>>(adj_rows, adj_cols, adj_vals, nnz_adj);

    // 1) XW1 = feat @ W_gc1 — fused split-3 fp16 (fp32-class)
    {
        dim3 grid(HID / 128, cdiv(NNODES, 128));
        hmma_gemm3_kernel<<<grid, 256, H_SMEM_TOTAL>>>(
            fhi, fhi, flo, whi_gc1, wlo_gc1, whi_gc1, bufA, NNODES, HID, 512, 512);
    }
    // 2) h = relu(spmm + b1) — CSR gather, split fp16 output
    spmm_gather_split_kernel<<<cdiv(NNODES, 8), TB>>>(off_enc, ecol, eval, bufA, b_gc1, hhi, hlo, NNODES);
    // 3) hW2 = h @ W_gc2 — fused split-3 fp16 (fp32-class)
    {
        dim3 grid(1, cdiv(NNODES, 128));
        hmma_gemm3_kernel<<<grid, 256, H_SMEM_TOTAL>>>(
            hhi, hhi, hlo, whi_gc2, wlo_gc2, whi_gc2, bufA, NNODES, LAT, 256, 256);
    }
    // 4) z = relu(spmm + b2)
    spmm_gather_kernel<64, false><<<cdiv(NNODES, 8), TB>>>(off_enc, ecol, eval, bufA, b_gc2, z, NNODES);
    // 5) degree + pred_deg
    degree_kernel<<<cdiv(NNODES, TB / 32), TB>>>(z, W_reg, b_reg, out_deg, pdeg, NNODES);
    // 5b) mend CSR build
    cudaMemsetAsync(cnt, 0, NODE_LEN * sizeof(int));
    mend_hist_edges_kernel<<<cdiv(E, TB), TB>>>(edges, E);
    mend_hist_new_kernel<<<cdiv(NNODES * NPRED, TB), TB>>>(pdeg);
    scan_kernel<<<1, 1024>>>(cnt, off_mend, fill, NODE_LEN);
    mend_fill_edges_kernel<<<cdiv(E, TB), TB>>>(edges, E);
    mend_fill_new_kernel<<<cdiv(NNODES * NPRED, TB), TB>>>(pdeg);
    // 6) znh = half(z + noise), zero-padded to K=128
    add_half_pad_kernel<<<cdiv((long long)NNODES * 128, TB), TB>>>(znh, z, noise);
    // 7) g1h = half(relu(znh @ W_fc1 + b)) — fp16 mma (K=128 padded)
    {
        dim3 grid(FC1N / 128, cdiv(NNODES, 128));
        hmma_gemm_kernel<1, 1><<<grid, 256, H_SMEM_TOTAL>>>(
            znh, wh_fc1, b_fc1, nullptr, g1h, NNODES, FC1N, 128, 128);
    }
    // 8) g2h = half(relu(g1h @ W_fc2 + b)) — fp16 mma
    {
        dim3 grid(FC2N / 128, cdiv(NNODES, 128));
        hmma_gemm_kernel<1, 1><<<grid, 256, H_SMEM_TOTAL>>>(
            g1h, wh_fc2, b_fc2, nullptr, g2h, NNODES, FC2N, FC1N, 256);
    }
    // 9) gen_feat = tanh(g2h @ W_flat + b) — WIDE 128x256 fp16 mma
    {
        dim3 grid(2560 / 256, cdiv(NNODES, 128));
        hmma_gemm_wide_kernel<2, 2><<<grid, 256, W_SMEM_TOTAL>>>(
            g2h, wh_flat, b_flat, out_gen, fillh, NNODES, GENF, FC2N, 2048);
    }
    // 10) fillW3 = fillh @ W_gc3 — fp16 mma, fp16 output
    {
        dim3 grid(HID / 128, cdiv(NODE_LEN, 128));
        hmma_gemm_kernel<0, 1><<<grid, 256, H_SMEM_TOTAL>>>(
            fillh, wh_gc3, nullptr, nullptr, fw3h, NODE_LEN, HID, 512, 512);
    }
    // 12) mend layer 1 — CSR gather (fp16 input), fused normalize+bias+relu
    mend_gather_h_kernel<<<cdiv(NODE_LEN, 8), TB>>>(off_mend, mcol, fw3h, b_gc3, bufB, NODE_LEN);
    // 13) c7 = h2 @ W_gc4 — skinny N=16
    skinny16_kernel<<<cdiv(NODE_LEN, 128), 128>>>(bufB, W_gc4, c7, NODE_LEN);
    // 14) mend layer 2 — CSR gather
    spmm_gather_kernel<16, true><<<cdiv(NODE_LEN, 8), TB>>>(off_mend, mcol, nullptr, c7, b_gc4, out_nc, NODE_LEN);

    (void)n_in; (void)out_size;
}

// round 16
// speedup vs baseline: 1.0763x; 1.0763x over previous
#include <cuda_runtime.h>
#include <cuda_fp16.h>
#include <cstdint>

// ---------------- problem constants ----------------
#define NNODES   20000
#define FEAT     500
#define HID      256
#define LAT      64
#define NPRED    5
#define NCLS     16
#define NODE_LEN (NNODES + NNODES * NPRED)      // 120000
#define GENF     (NPRED * FEAT)                 // 2500
#define FC1N     256
#define FC2N     2048

#define OUT_GEN_OFF ((long long)NNODES)
#define OUT_NC_OFF  ((long long)NNODES + (long long)NNODES * GENF)

// ---------------- scratch (static device globals; no allocation) ------------
__device__ float g_bufA[(size_t)NNODES * HID];
__device__ float g_z[(size_t)NNODES * LAT];
__device__ float g_c7[(size_t)NODE_LEN * NCLS];
__device__ int   g_pdeg[NNODES];
__device__ int   g_is64;
// fp16 operands
__device__ __half g_g1h[(size_t)NNODES * FC1N];
__device__ __half g_g2h[(size_t)NNODES * FC2N];
__device__ __half g_fillh[(size_t)NODE_LEN * 512];
__device__ __half g_fw3h[(size_t)NODE_LEN * HID];
__device__ __half g_h2h[(size_t)NODE_LEN * HID];
__device__ __half g_fhi[(size_t)NNODES * 512];
__device__ __half g_flo[(size_t)NNODES * 512];
__device__ __half g_hhi[(size_t)NNODES * 256];
__device__ __half g_hlo[(size_t)NNODES * 256];
__device__ __half g_znh[(size_t)NNODES * 128];
__device__ __half g_wh_fc2[(size_t)2048 * 256];
__device__ __half g_wh_flat[(size_t)2560 * 2048];
__device__ __half g_wh_gc3[(size_t)256 * 512];
__device__ __half g_wh_fc1[(size_t)256 * 128];
__device__ __half g_whi_gc1[(size_t)256 * 512];
__device__ __half g_wlo_gc1[(size_t)256 * 512];
__device__ __half g_whi_gc2[(size_t)128 * 256];
__device__ __half g_wlo_gc2[(size_t)128 * 256];
// CSR scratch
__device__ int   g_cnt[NODE_LEN];
__device__ int   g_fill[NODE_LEN];
__device__ int   g_off_enc[NNODES + 1];
__device__ int   g_off_mend[NODE_LEN + 1];
__device__ int   g_ecol[700000];
__device__ float g_eval[700000];
__device__ int   g_mcol[900000];

// ---------------- helpers ----------------
__device__ __forceinline__ uint32_t smem_u32(const void* p) {
    uint32_t a;
    asm("{ .reg .u64 t; cvta.to.shared.u64 t, %1; cvt.u32.u64 %0, t; }" : "=r"(a) : "l"(p));
    return a;
}
__device__ __forceinline__ void ldsm_x4(uint32_t addr, uint32_t* r) {
    asm volatile("ldmatrix.sync.aligned.m8n8.x4.shared.b16 {%0,%1,%2,%3}, [%4];"
                 : "=r"(r[0]), "=r"(r[1]), "=r"(r[2]), "=r"(r[3]) : "r"(addr));
}
__device__ __forceinline__ void mma_f16(float* c, const uint32_t* a, uint32_t b0, uint32_t b1) {
    asm volatile(
        "mma.sync.aligned.m16n8k16.row.col.f32.f16.f16.f32 "
        "{%0,%1,%2,%3}, {%4,%5,%6,%7}, {%8,%9}, {%0,%1,%2,%3};"
        : "+f"(c[0]), "+f"(c[1]), "+f"(c[2]), "+f"(c[3])
        : "r"(a[0]), "r"(a[1]), "r"(a[2]), "r"(a[3]), "r"(b0), "r"(b1));
}
#define CP_ASYNC16(dst, src) \
    asm volatile("cp.async.cg.shared.global [%0], [%1], 16;" :: "r"(dst), "l"(src))
#define CP_COMMIT() asm volatile("cp.async.commit_group;" ::: "memory")
#define CP_WAIT(n)  asm volatile("cp.async.wait_group %0;" :: "n"(n) : "memory")

// ---------------- index dtype detection ----------------
__global__ void detect_idx_kernel(const void* adj_rows) {
    int lane = threadIdx.x;
    const long long* p = (const long long*)adj_rows;
    int bad = 0;
    for (int i = lane; i < 256; i += 32) {
        long long v = p[i];
        if (v < 0 || v >= NODE_LEN) bad = 1;
    }
    unsigned m = __ballot_sync(0xffffffffu, bad);
    if (lane == 0) g_is64 = (m == 0) ? 1 : 0;
}
__device__ __forceinline__ long long load_idx(const void* p, long long i) {
    return g_is64 ? ((const long long*)p)[i] : (long long)((const int*)p)[i];
}

// ---------------- CSR build ----------------
__global__ void enc_hist_kernel(const void* __restrict__ rows, long long nnz) {
    long long e = (long long)blockIdx.x * blockDim.x + threadIdx.x;
    if (e >= nnz) return;
    atomicAdd(&g_cnt[load_idx(rows, e)], 1);
}
__global__ void enc_fill_kernel(const void* __restrict__ rows, const void* __restrict__ cols,
                                const float* __restrict__ vals, long long nnz) {
    long long e = (long long)blockIdx.x * blockDim.x + threadIdx.x;
    if (e >= nnz) return;
    int r = (int)load_idx(rows, e);
    int pos = atomicAdd(&g_fill[r], 1);
    g_ecol[pos] = (int)load_idx(cols, e);
    g_eval[pos] = vals[e];
}
__global__ void scan_kernel(const int* __restrict__ cnt, int* __restrict__ off,
                            int* __restrict__ fill, int n) {
    __shared__ int part[1024];
    int t = threadIdx.x;
    int chunk = (n + 1023) >> 10;
    int lo = t * chunk, hi = lo + chunk;
    if (hi > n) hi = n;
    int s = 0;
    for (int i = lo; i < hi; i++) s += cnt[i];
    part[t] = s;
    __syncthreads();
    for (int d = 1; d < 1024; d <<= 1) {
        int add = (t >= d) ? part[t - d] : 0;
        __syncthreads();
        part[t] += add;
        __syncthreads();
    }
    int run = part[t] - s;
    for (int i = lo; i < hi; i++) {
        off[i] = run; fill[i] = run;
        run += cnt[i];
    }
    if (t == 1023) off[n] = part[1023];
}
__global__ void mend_hist_edges_kernel(const void* __restrict__ edges, int E) {
    int e = blockIdx.x * blockDim.x + threadIdx.x;
    if (e >= E) return;
    int lo = (int)load_idx(edges, 2LL * e);
    int hi = (int)load_idx(edges, 2LL * e + 1);
    atomicAdd(&g_cnt[lo], 1);
    atomicAdd(&g_cnt[hi], 1);
}
__global__ void mend_hist_new_kernel(const int* __restrict__ pdeg) {
    int t = blockIdx.x * blockDim.x + threadIdx.x;
    if (t >= NNODES * NPRED) return;
    int node = t / NPRED, j = t - node * NPRED;
    if (j < pdeg[node]) {
        atomicAdd(&g_cnt[node], 1);
        g_cnt[NNODES + t] = 1;
    }
}
__global__ void mend_fill_edges_kernel(const void* __restrict__ edges, int E) {
    int e = blockIdx.x * blockDim.x + threadIdx.x;
    if (e >= E) return;
    int lo = (int)load_idx(edges, 2LL * e);
    int hi = (int)load_idx(edges, 2LL * e + 1);
    int p0 = atomicAdd(&g_fill[lo], 1);
    g_mcol[p0] = hi;
    int p1 = atomicAdd(&g_fill[hi], 1);
    g_mcol[p1] = lo;
}
__global__ void mend_fill_new_kernel(const int* __restrict__ pdeg) {
    int t = blockIdx.x * blockDim.x + threadIdx.x;
    if (t >= NNODES * NPRED) return;
    int node = t / NPRED, j = t - node * NPRED;
    if (j < pdeg[node]) {
        int p0 = atomicAdd(&g_fill[node], 1);
        g_mcol[p0] = NNODES + t;
        g_mcol[g_off_mend[NNODES + t]] = node;
    }
}

// ---------------- gather SpMM (warp per row) ----------------
template <int D, bool MEND>
__global__ void spmm_gather_kernel(const int* __restrict__ off, const int* __restrict__ cols,
                                   const float* __restrict__ vals,
                                   const float* __restrict__ x, const float* __restrict__ bias,
                                   float* __restrict__ y, int nrows)
{
    int w = (int)(((long long)blockIdx.x * blockDim.x + threadIdx.x) >> 5);
    int lane = threadIdx.x & 31;
    if (w >= nrows) return;
    int e0 = off[w], e1 = off[w + 1];

    if (D == 64) {
        float a0 = 0.f, a1 = 0.f;
        const int cb = lane * 2;
        for (int e = e0; e < e1; e++) {
            long long c = cols[e];
            float2 t = *(const float2*)(x + c * 64 + cb);
            float v = vals[e];
            a0 += v * t.x; a1 += v * t.y;
        }
        float2 o;
        o.x = fmaxf(a0 + bias[cb + 0], 0.f);
        o.y = fmaxf(a1 + bias[cb + 1], 0.f);
        *(float2*)(y + (long long)w * 64 + cb) = o;
    } else {  // D == 16, MEND
        if (lane < 16) {
            float a = 0.f;
            for (int e = e0; e < e1; e++)
                a += x[(long long)cols[e] * 16 + lane];
            float inv = 1.0f / (1.0f + (float)(e1 - e0));
            float v = (a + x[(long long)w * 16 + lane]) * inv + bias[lane];
            y[(long long)w * 16 + lane] = fmaxf(v, 0.f);
        }
    }
}

// mend layer-1 gather: fp16 input, f32 accumulate, fp16 output (feeds skinny16_h)
__global__ void mend_gather_h_kernel(const int* __restrict__ off, const int* __restrict__ cols,
                                     const __half* __restrict__ xh, const float* __restrict__ bias,
                                     __half* __restrict__ y, int nrows)
{
    int w = (int)(((long long)blockIdx.x * blockDim.x + threadIdx.x) >> 5);
    int lane = threadIdx.x & 31;
    if (w >= nrows) return;
    int e0 = off[w], e1 = off[w + 1];

    float a[8] = {0, 0, 0, 0, 0, 0, 0, 0};
    const int cb = lane * 8;
    for (int e = e0; e < e1; e++) {
        long long c = cols[e];
        const __half2* px = (const __half2*)(xh + c * 256 + cb);
        __half2 h0 = px[0], h1 = px[1], h2 = px[2], h3 = px[3];
        float2 f0 = __half22float2(h0), f1 = __half22float2(h1);
        float2 f2 = __half22float2(h2), f3 = __half22float2(h3);
        a[0] += f0.x; a[1] += f0.y; a[2] += f1.x; a[3] += f1.y;
        a[4] += f2.x; a[5] += f2.y; a[6] += f3.x; a[7] += f3.y;
    }
    float inv = 1.0f / (1.0f + (float)(e1 - e0));
    const __half2* pr = (const __half2*)(xh + (long long)w * 256 + cb);
    __half2 r0 = pr[0], r1 = pr[1], r2 = pr[2], r3 = pr[3];
    float xr[8];
    {
        float2 f0 = __half22float2(r0), f1 = __half22float2(r1);
        float2 f2 = __half22float2(r2), f3 = __half22float2(r3);
        xr[0] = f0.x; xr[1] = f0.y; xr[2] = f1.x; xr[3] = f1.y;
        xr[4] = f2.x; xr[5] = f2.y; xr[6] = f3.x; xr[7] = f3.y;
    }
    float v[8];
#pragma unroll
    for (int q = 0; q < 8; q++)
        v[q] = fmaxf((a[q] + xr[q]) * inv + bias[cb + q], 0.f);
    __half2* py = (__half2*)(y + (long long)w * 256 + cb);
    py[0] = __floats2half2_rn(v[0], v[1]);
    py[1] = __floats2half2_rn(v[2], v[3]);
    py[2] = __floats2half2_rn(v[4], v[5]);
    py[3] = __floats2half2_rn(v[6], v[7]);
}

// encoder gather D=256 writing split fp16 (hi, lo)
__global__ void spmm_gather_split_kernel(const int* __restrict__ off, const int* __restrict__ cols,
                                         const float* __restrict__ vals,
                                         const float* __restrict__ x, const float* __restrict__ bias,
                                         __half* __restrict__ yhi, __half* __restrict__ ylo, int nrows)
{
    int w = (int)(((long long)blockIdx.x * blockDim.x + threadIdx.x) >> 5);
    int lane = threadIdx.x & 31;
    if (w >= nrows) return;
    int e0 = off[w], e1 = off[w + 1];
    float a[8] = {0, 0, 0, 0, 0, 0, 0, 0};
    const int cb = lane * 4;
    for (int e = e0; e < e1; e++) {
        long long c = cols[e];
        float4 t0 = *(const float4*)(x + c * 256 + cb);
        float4 t1 = *(const float4*)(x + c * 256 + 128 + cb);
        float v = vals[e];
        a[0] += v * t0.x; a[1] += v * t0.y; a[2] += v * t0.z; a[3] += v * t0.w;
        a[4] += v * t1.x; a[5] += v * t1.y; a[6] += v * t1.z; a[7] += v * t1.w;
    }
#pragma unroll
    for (int g = 0; g < 2; g++) {
        int base = g * 128 + cb;
        float v0 = fmaxf(a[4 * g + 0] + bias[base + 0], 0.f);
        float v1 = fmaxf(a[4 * g + 1] + bias[base + 1], 0.f);
        float v2 = fmaxf(a[4 * g + 2] + bias[base + 2], 0.f);
        float v3 = fmaxf(a[4 * g + 3] + bias[base + 3], 0.f);
        __half h0 = __float2half_rn(v0), h1 = __float2half_rn(v1);
        __half h2 = __float2half_rn(v2), h3 = __float2half_rn(v3);
        long long o = (long long)w * 256 + base;
        *(__half2*)(yhi + o)     = __halves2half2(h0, h1);
        *(__half2*)(yhi + o + 2) = __halves2half2(h2, h3);
        *(__half2*)(ylo + o)     = __halves2half2(__float2half_rn(v0 - __half2float(h0)),
                                                  __float2half_rn(v1 - __half2float(h1)));
        *(__half2*)(ylo + o + 2) = __halves2half2(__float2half_rn(v2 - __half2float(h2)),
                                                  __float2half_rn(v3 - __half2float(h3)));
    }
}

// ---------------- weight transpose -> half ----------------
__global__ void transpose_half_kernel(const float* __restrict__ W, __half* __restrict__ WT,
                                      int K, int N, int Kpad, int Npad) {
    __shared__ float tile[32][33];
    int kb = blockIdx.x * 32, nb = blockIdx.y * 32;
    int tx = threadIdx.x, ty = threadIdx.y;   // 32 x 8
#pragma unroll
    for (int i = 0; i < 4; i++) {
        int k = kb + ty + i * 8, n = nb + tx;
        tile[ty + i * 8][tx] = (k < K && n < N) ? W[(long long)k * N + n] : 0.0f;
    }
    __syncthreads();
#pragma unroll
    for (int i = 0; i < 4; i++) {
        int n = nb + ty + i * 8, k = kb + tx;
        if (n < Npad && k < Kpad)
            WT[(long long)n * Kpad + k] = __float2half_rn(tile[tx][ty + i * 8]);
    }
}
__global__ void transpose_half_split_kernel(const float* __restrict__ W,
                                            __half* __restrict__ WThi, __half* __restrict__ WTlo,
                                            int K, int N, int Kpad, int Npad) {
    __shared__ float tile[32][33];
    int kb = blockIdx.x * 32, nb = blockIdx.y * 32;
    int tx = threadIdx.x, ty = threadIdx.y;
#pragma unroll
    for (int i = 0; i < 4; i++) {
        int k = kb + ty + i * 8, n = nb + tx;
        tile[ty + i * 8][tx] = (k < K && n < N) ? W[(long long)k * N + n] : 0.0f;
    }
    __syncthreads();
#pragma unroll
    for (int i = 0; i < 4; i++) {
        int n = nb + ty + i * 8, k = kb + tx;
        if (n < Npad && k < Kpad) {
            float v = tile[tx][ty + i * 8];
            __half h = __float2half_rn(v);
            WThi[(long long)n * Kpad + k] = h;
            WTlo[(long long)n * Kpad + k] = __float2half_rn(v - __half2float(h));
        }
    }
}
__global__ void feat_prep_kernel(const float* __restrict__ feat,
                                 __half* __restrict__ fhi, __half* __restrict__ flo,
                                 __half* __restrict__ fillh) {
    long long i = (long long)blockIdx.x * blockDim.x + threadIdx.x;
    if (i >= (long long)NNODES * 512) return;
    int r = (int)(i >> 9), c = (int)(i & 511);
    float v = (c < FEAT) ? feat[(long long)r * FEAT + c] : 0.0f;
    __half h = __float2half_rn(v);
    fhi[i] = h;
    flo[i] = __float2half_rn(v - __half2float(h));
    fillh[i] = h;
}
__global__ void add_half_pad_kernel(__half* __restrict__ o, const float* __restrict__ a,
                                    const float* __restrict__ b)
{
    long long i = (long long)blockIdx.x * blockDim.x + threadIdx.x;
    if (i >= (long long)NNODES * 128) return;
    int r = (int)(i >> 7), c = (int)(i & 127);
    o[i] = (c < LAT) ? __float2half_rn(a[(long long)r * LAT + c] + b[(long long)r * LAT + c])
                     : __half(0.0f);
}

// ---------------- fp16 mma GEMM (128x128) ------------------
#define HSTAGES 4
#define H_STRIDE_B 80
#define H_MAT_BYTES (128 * H_STRIDE_B)          // 10240
#define H_STAGE_BYTES (2 * H_MAT_BYTES)         // 20480
#define H_SMEM_TOTAL (HSTAGES * H_STAGE_BYTES)  // 81920

// EPI: 0 none, 1 bias+relu, 2 bias+tanh.  OUT: 0 f32 C, 1 half Ch, 2 f32 C + genh->fillh
template <int EPI, int OUT>
__global__ void __launch_bounds__(256, 2) hmma_gemm_kernel(
    const __half* __restrict__ A, const __half* __restrict__ BT,
    const float* __restrict__ bias,
    float* __restrict__ C, __half* __restrict__ Ch,
    int M, int N, int K, int Kpad)
{
    extern __shared__ char smem[];
    const uint32_t sbase = smem_u32(smem);
    const int tid = threadIdx.x;
    const int wid = tid >> 5, lane = tid & 31;
    const int gid = lane >> 2, tig = lane & 3;
    const int warp_m = wid & 3, warp_n = wid >> 2;
    const int m0 = blockIdx.y * 128, n0 = blockIdx.x * 128;

    const int crow = tid >> 1;
    const int cboff = (tid & 1) * 32;

    const __half* aptr;
    {
        int r = m0 + crow;
        int rr = (r < M) ? r : (M - 1);
        aptr = A + (long long)rr * K;
    }
    const __half* bptr = BT + (long long)(n0 + crow) * Kpad;

    const uint32_t sA_wr = sbase + (uint32_t)crow * H_STRIDE_B + (uint32_t)cboff;
    const uint32_t sB_wr = sA_wr + H_MAT_BYTES;

    const int nChunks = K >> 5;

    auto issue = [&](int chunk) {
        int s = chunk & (HSTAGES - 1);
        uint32_t da = sA_wr + (uint32_t)s * H_STAGE_BYTES;
        uint32_t db = sB_wr + (uint32_t)s * H_STAGE_BYTES;
        const char* ga = (const char*)aptr + chunk * 64 + cboff;
        const char* gb = (const char*)bptr + chunk * 64 + cboff;
        CP_ASYNC16(da, ga); CP_ASYNC16(da + 16, ga + 16);
        CP_ASYNC16(db, gb); CP_ASYNC16(db + 16, gb + 16);
        CP_COMMIT();
    };

    float acc[2][8][4];
#pragma unroll
    for (int f = 0; f < 2; f++)
#pragma unroll
        for (int j = 0; j < 8; j++)
#pragma unroll
            for (int q = 0; q < 4; q++) acc[f][j][q] = 0.0f;

    for (int s = 0; s < HSTAGES - 1; s++) issue(s);

    uint32_t a_off[2];
#pragma unroll
    for (int f = 0; f < 2; f++) {
        uint32_t row = (uint32_t)(warp_m * 32 + f * 16 + (lane & 15));
        uint32_t colb = (uint32_t)((lane >> 4) << 4);
        a_off[f] = row * H_STRIDE_B + colb;
    }
    uint32_t b_off[4];
#pragma unroll
    for (int jp = 0; jp < 4; jp++) {
        uint32_t row = (uint32_t)(warp_n * 64 + jp * 16 + ((lane >> 4) << 3) + (lane & 7));
        uint32_t colb = (uint32_t)(((lane >> 3) & 1) << 4);
        b_off[jp] = row * H_STRIDE_B + colb;
    }

    CP_WAIT(HSTAGES - 2);
    __syncthreads();

    for (int i = 0; i < nChunks; i++) {
        uint32_t sA = sbase + (uint32_t)(i & (HSTAGES - 1)) * H_STAGE_BYTES;
        uint32_t sB = sA + H_MAT_BYTES;
#pragma unroll
        for (int kk = 0; kk < 2; kk++) {
            uint32_t afr[2][4];
            ldsm_x4(sA + a_off[0] + kk * 32, afr[0]);
            ldsm_x4(sA + a_off[1] + kk * 32, afr[1]);
#pragma unroll
            for (int jp = 0; jp < 4; jp++) {
                uint32_t br[4];
                ldsm_x4(sB + b_off[jp] + kk * 32, br);
                mma_f16(acc[0][2 * jp + 0], afr[0], br[0], br[1]);
                mma_f16(acc[1][2 * jp + 0], afr[1], br[0], br[1]);
                mma_f16(acc[0][2 * jp + 1], afr[0], br[2], br[3]);
                mma_f16(acc[1][2 * jp + 1], afr[1], br[2], br[3]);
            }
        }
        if (i + HSTAGES - 1 < nChunks) issue(i + HSTAGES - 1);
        else CP_COMMIT();
        CP_WAIT(HSTAGES - 2);
        __syncthreads();
    }

#pragma unroll
    for (int f = 0; f < 2; f++) {
#pragma unroll
        for (int rr = 0; rr < 2; rr++) {
            int r = m0 + warp_m * 32 + f * 16 + rr * 8 + gid;
            if (r >= M) continue;
#pragma unroll
            for (int j = 0; j < 8; j++) {
                int c = n0 + warp_n * 64 + j * 8 + tig * 2;
                if (c >= N) continue;
                float v0 = acc[f][j][rr * 2 + 0], v1 = acc[f][j][rr * 2 + 1];
                if (EPI >= 1) { v0 += bias[c]; v1 += bias[c + 1]; }
                if (EPI == 1) { v0 = fmaxf(v0, 0.f); v1 = fmaxf(v1, 0.f); }
                if (EPI == 2) { v0 = tanhf(v0); v1 = tanhf(v1); }
                if (OUT == 0) {
                    *(float2*)(C + (long long)r * N + c) = make_float2(v0, v1);
                } else if (OUT == 1) {
                    *(__half2*)(Ch + (long long)r * N + c) = __floats2half2_rn(v0, v1);
                } else {
                    *(float2*)(C + (long long)r * N + c) = make_float2(v0, v1);
                    int j5 = c / FEAT, cc = c - j5 * FEAT;
                    *(__half2*)(Ch + ((size_t)(NNODES + r * NPRED + j5) * 512 + cc)) =
                        __floats2half2_rn(v0, v1);
                }
            }
        }
    }
}

// ---------------- triple-pass split-3 GEMM: C = A0@B0 + A1@B1 + A2@B2 ------
__global__ void __launch_bounds__(256, 2) hmma_gemm3_kernel(
    const __half* __restrict__ A0, const __half* __restrict__ A1, const __half* __restrict__ A2,
    const __half* __restrict__ B0, const __half* __restrict__ B1, const __half* __restrict__ B2,
    float* __restrict__ C, int M, int N, int K, int Kpad)
{
    extern __shared__ char smem[];
    const uint32_t sbase = smem_u32(smem);
    const int tid = threadIdx.x;
    const int wid = tid >> 5, lane = tid & 31;
    const int gid = lane >> 2, tig = lane & 3;
    const int warp_m = wid & 3, warp_n = wid >> 2;
    const int m0 = blockIdx.y * 128, n0 = blockIdx.x * 128;

    const int crow = tid >> 1;
    const int cboff = (tid & 1) * 32;

    int rr = (m0 + crow < M) ? (m0 + crow) : (M - 1);
    const __half* ap0 = A0 + (long long)rr * K;
    const __half* ap1 = A1 + (long long)rr * K;
    const __half* ap2 = A2 + (long long)rr * K;
    const __half* bp0 = B0 + (long long)(n0 + crow) * Kpad;
    const __half* bp1 = B1 + (long long)(n0 + crow) * Kpad;
    const __half* bp2 = B2 + (long long)(n0 + crow) * Kpad;

    const uint32_t sA_wr = sbase + (uint32_t)crow * H_STRIDE_B + (uint32_t)cboff;
    const uint32_t sB_wr = sA_wr + H_MAT_BYTES;

    const int nChunks = K >> 5;
    const int total = 3 * nChunks;

    auto issue = [&](int t) {
        int pass = t / nChunks;
        int local = t - pass * nChunks;
        const __half* ga = (pass == 0) ? ap0 : (pass == 1) ? ap1 : ap2;
        const __half* gb = (pass == 0) ? bp0 : (pass == 1) ? bp1 : bp2;
        int s = t & (HSTAGES - 1);
        uint32_t da = sA_wr + (uint32_t)s * H_STAGE_BYTES;
        uint32_t db = sB_wr + (uint32_t)s * H_STAGE_BYTES;
        const char* pa = (const char*)ga + local * 64 + cboff;
        const char* pb = (const char*)gb + local * 64 + cboff;
        CP_ASYNC16(da, pa); CP_ASYNC16(da + 16, pa + 16);
        CP_ASYNC16(db, pb); CP_ASYNC16(db + 16, pb + 16);
        CP_COMMIT();
    };

    float acc[2][8][4];
#pragma unroll
    for (int f = 0; f < 2; f++)
#pragma unroll
        for (int j = 0; j < 8; j++)
#pragma unroll
            for (int q = 0; q < 4; q++) acc[f][j][q] = 0.0f;

    for (int s = 0; s < HSTAGES - 1; s++) issue(s);

    uint32_t a_off[2];
#pragma unroll
    for (int f = 0; f < 2; f++) {
        uint32_t row = (uint32_t)(warp_m * 32 + f * 16 + (lane & 15));
        uint32_t colb = (uint32_t)((lane >> 4) << 4);
        a_off[f] = row * H_STRIDE_B + colb;
    }
    uint32_t b_off[4];
#pragma unroll
    for (int jp = 0; jp < 4; jp++) {
        uint32_t row = (uint32_t)(warp_n * 64 + jp * 16 + ((lane >> 4) << 3) + (lane & 7));
        uint32_t colb = (uint32_t)(((lane >> 3) & 1) << 4);
        b_off[jp] = row * H_STRIDE_B + colb;
    }

    CP_WAIT(HSTAGES - 2);
    __syncthreads();

    for (int i = 0; i < total; i++) {
        uint32_t sA = sbase + (uint32_t)(i & (HSTAGES - 1)) * H_STAGE_BYTES;
        uint32_t sB = sA + H_MAT_BYTES;
#pragma unroll
        for (int kk = 0; kk < 2; kk++) {
            uint32_t afr[2][4];
            ldsm_x4(sA + a_off[0] + kk * 32, afr[0]);
            ldsm_x4(sA + a_off[1] + kk * 32, afr[1]);
#pragma unroll
            for (int jp = 0; jp < 4; jp++) {
                uint32_t br[4];
                ldsm_x4(sB + b_off[jp] + kk * 32, br);
                mma_f16(acc[0][2 * jp + 0], afr[0], br[0], br[1]);
                mma_f16(acc[1][2 * jp + 0], afr[1], br[0], br[1]);
                mma_f16(acc[0][2 * jp + 1], afr[0], br[2], br[3]);
                mma_f16(acc[1][2 * jp + 1], afr[1], br[2], br[3]);
            }
        }
        if (i + HSTAGES - 1 < total) issue(i + HSTAGES - 1);
        else CP_COMMIT();
        CP_WAIT(HSTAGES - 2);
        __syncthreads();
    }

#pragma unroll
    for (int f = 0; f < 2; f++) {
#pragma unroll
        for (int rr2 = 0; rr2 < 2; rr2++) {
            int r = m0 + warp_m * 32 + f * 16 + rr2 * 8 + gid;
            if (r >= M) continue;
#pragma unroll
            for (int j = 0; j < 8; j++) {
                int c = n0 + warp_n * 64 + j * 8 + tig * 2;
                if (c >= N) continue;
                *(float2*)(C + (long long)r * N + c) =
                    make_float2(acc[f][j][rr2 * 2 + 0], acc[f][j][rr2 * 2 + 1]);
            }
        }
    }
}

// ---------------- skinny GEMM for gc4 (fp16 input) ----------------
__global__ void skinny16_h_kernel(const __half* __restrict__ X, const float* __restrict__ W,
                                  float* __restrict__ C, int M)
{
    __shared__ float Ws[256 * 16];
    int tid = threadIdx.x;   // 128
    for (int i = tid; i < 256 * 16; i += 128) Ws[i] = W[i];
    __syncthreads();
    int r = blockIdx.x * 128 + tid;
    if (r >= M) return;
    const __half2* x = (const __half2*)(X + (long long)r * 256);
    float acc[16];
#pragma unroll
    for (int q = 0; q < 16; q++) acc[q] = 0.0f;
    for (int k2 = 0; k2 < 128; k2 += 2) {
        float2 a0 = __half22float2(x[k2]);
        float2 a1 = __half22float2(x[k2 + 1]);
        int k = k2 * 2;
#pragma unroll
        for (int q = 0; q < 16; q++)
            acc[q] += a0.x * Ws[(k + 0) * 16 + q] + a0.y * Ws[(k + 1) * 16 + q]
                    + a1.x * Ws[(k + 2) * 16 + q] + a1.y * Ws[(k + 3) * 16 + q];
    }
    float* co = C + (long long)r * 16;
#pragma unroll
    for (int q = 0; q < 16; q += 4)
        *(float4*)(co + q) = make_float4(acc[q], acc[q + 1], acc[q + 2], acc[q + 3]);
}

// ---------------- misc ----------------
__global__ void degree_kernel(const float* __restrict__ z, const float* __restrict__ Wr,
                              const float* __restrict__ br, float* __restrict__ deg_out,
                              int* __restrict__ pdeg, int n)
{
    int r = blockIdx.x * (blockDim.x >> 5) + (threadIdx.x >> 5);
    int lane = threadIdx.x & 31;
    if (r >= n) return;
    float s = z[(long long)r * LAT + lane] * Wr[lane]
            + z[(long long)r * LAT + 32 + lane] * Wr[32 + lane];
#pragma unroll
    for (int o = 16; o; o >>= 1) s += __shfl_xor_sync(0xffffffffu, s, o);
    if (lane == 0) {
        float d = fmaxf(s + br[0], 0.0f);
        deg_out[r] = d;
        int pi = (int)d;
        if (pi > NPRED) pi = NPRED;
        pdeg[r] = pi;
    }
}

// ---------------- host ----------------
static inline int cdiv(long long a, long long b) { return (int)((a + b - 1) / b); }

extern "C" void kernel_launch(void* const* d_in, const int* in_sizes, int n_in,
                              void* d_out, int out_size)
{
    const float* feat     = (const float*)d_in[0];
    const void*  edges    = d_in[1];
    const void*  adj_rows = d_in[2];
    const void*  adj_cols = d_in[3];
    const float* adj_vals = (const float*)d_in[4];
    const float* noise    = (const float*)d_in[5];
    const float* W_gc1 = (const float*)d_in[6];   const float* b_gc1 = (const float*)d_in[7];
    const float* W_gc2 = (const float*)d_in[8];   const float* b_gc2 = (const float*)d_in[9];
    const float* W_reg = (const float*)d_in[10];  const float* b_reg = (const float*)d_in[11];
    const float* W_fc1 = (const float*)d_in[12];  const float* b_fc1 = (const float*)d_in[13];
    const float* W_fc2 = (const float*)d_in[14];  const float* b_fc2 = (const float*)d_in[15];
    const float* W_flat = (const float*)d_in[16]; const float* b_flat = (const float*)d_in[17];
    const float* W_gc3 = (const float*)d_in[18];  const float* b_gc3 = (const float*)d_in[19];
    const float* W_gc4 = (const float*)d_in[20];  const float* b_gc4 = (const float*)d_in[21];

    float* out = (float*)d_out;
    float* out_deg = out;
    float* out_gen = out + OUT_GEN_OFF;
    float* out_nc  = out + OUT_NC_OFF;

    const long long nnz_adj = in_sizes[2];
    const int E = in_sizes[1] / 2;

    void* p;
    float *bufA, *z, *c7;
    __half *g1h, *g2h, *fillh, *fw3h, *h2h, *fhi, *flo, *hhi, *hlo, *znh;
    __half *wh_fc2, *wh_flat, *wh_gc3, *wh_fc1, *whi_gc1, *wlo_gc1, *whi_gc2, *wlo_gc2;
    int *pdeg, *cnt, *fill, *off_enc, *off_mend, *ecol, *mcol;
    float *eval;
    cudaGetSymbolAddress(&p, g_bufA);  bufA  = (float*)p;
    cudaGetSymbolAddress(&p, g_z);     z     = (float*)p;
    cudaGetSymbolAddress(&p, g_c7);    c7    = (float*)p;
    cudaGetSymbolAddress(&p, g_pdeg);  pdeg  = (int*)p;
    cudaGetSymbolAddress(&p, g_cnt);   cnt   = (int*)p;
    cudaGetSymbolAddress(&p, g_fill);  fill  = (int*)p;
    cudaGetSymbolAddress(&p, g_off_enc);  off_enc  = (int*)p;
    cudaGetSymbolAddress(&p, g_off_mend); off_mend = (int*)p;
    cudaGetSymbolAddress(&p, g_ecol);  ecol  = (int*)p;
    cudaGetSymbolAddress(&p, g_eval);  eval  = (float*)p;
    cudaGetSymbolAddress(&p, g_mcol);  mcol  = (int*)p;
    cudaGetSymbolAddress(&p, g_g1h);   g1h   = (__half*)p;
    cudaGetSymbolAddress(&p, g_g2h);   g2h   = (__half*)p;
    cudaGetSymbolAddress(&p, g_fillh); fillh = (__half*)p;
    cudaGetSymbolAddress(&p, g_fw3h);  fw3h  = (__half*)p;
    cudaGetSymbolAddress(&p, g_h2h);   h2h   = (__half*)p;
    cudaGetSymbolAddress(&p, g_fhi);   fhi   = (__half*)p;
    cudaGetSymbolAddress(&p, g_flo);   flo   = (__half*)p;
    cudaGetSymbolAddress(&p, g_hhi);   hhi   = (__half*)p;
    cudaGetSymbolAddress(&p, g_hlo);   hlo   = (__half*)p;
    cudaGetSymbolAddress(&p, g_znh);   znh   = (__half*)p;
    cudaGetSymbolAddress(&p, g_wh_fc2);  wh_fc2  = (__half*)p;
    cudaGetSymbolAddress(&p, g_wh_flat); wh_flat = (__half*)p;
    cudaGetSymbolAddress(&p, g_wh_gc3);  wh_gc3  = (__half*)p;
    cudaGetSymbolAddress(&p, g_wh_fc1);  wh_fc1  = (__half*)p;
    cudaGetSymbolAddress(&p, g_whi_gc1); whi_gc1 = (__half*)p;
    cudaGetSymbolAddress(&p, g_wlo_gc1); wlo_gc1 = (__half*)p;
    cudaGetSymbolAddress(&p, g_whi_gc2); whi_gc2 = (__half*)p;
    cudaGetSymbolAddress(&p, g_wlo_gc2); wlo_gc2 = (__half*)p;

    cudaFuncSetAttribute((const void*)hmma_gemm_kernel<0, 1>,
                         cudaFuncAttributeMaxDynamicSharedMemorySize, H_SMEM_TOTAL);
    cudaFuncSetAttribute((const void*)hmma_gemm_kernel<1, 1>,
                         cudaFuncAttributeMaxDynamicSharedMemorySize, H_SMEM_TOTAL);
    cudaFuncSetAttribute((const void*)hmma_gemm_kernel<2, 2>,
                         cudaFuncAttributeMaxDynamicSharedMemorySize, H_SMEM_TOTAL);
    cudaFuncSetAttribute((const void*)hmma_gemm3_kernel,
                         cudaFuncAttributeMaxDynamicSharedMemorySize, H_SMEM_TOTAL);

    const int TB = 256;
    dim3 tblk(32, 8);

    // 0) prep
    detect_idx_kernel<<<1, 32>>>(adj_rows);
    transpose_half_kernel<<<dim3(cdiv(256, 32), cdiv(2048, 32)), tblk>>>(W_fc2, wh_fc2, 256, 2048, 256, 2048);
    transpose_half_kernel<<<dim3(cdiv(2048, 32), cdiv(2560, 32)), tblk>>>(W_flat, wh_flat, 2048, 2500, 2048, 2560);
    transpose_half_kernel<<<dim3(cdiv(512, 32), cdiv(256, 32)), tblk>>>(W_gc3, wh_gc3, 500, 256, 512, 256);
    transpose_half_kernel<<<dim3(cdiv(128, 32), cdiv(256, 32)), tblk>>>(W_fc1, wh_fc1, 64, 256, 128, 256);
    transpose_half_split_kernel<<<dim3(cdiv(512, 32), cdiv(256, 32)), tblk>>>(W_gc1, whi_gc1, wlo_gc1, 500, 256, 512, 256);
    transpose_half_split_kernel<<<dim3(cdiv(256, 32), cdiv(128, 32)), tblk>>>(W_gc2, whi_gc2, wlo_gc2, 256, 64, 256, 128);
    feat_prep_kernel<<<cdiv((long long)NNODES * 512, TB), TB>>>(feat, fhi, flo, fillh);

    // 0b) encoder CSR build
    cudaMemsetAsync(cnt, 0, NNODES * sizeof(int));
    enc_hist_kernel<<<cdiv(nnz_adj, TB), TB>>>(adj_rows, nnz_adj);
    scan_kernel<<<1, 1024>>>(cnt, off_enc, fill, NNODES);
    enc_fill_kernel<<<cdiv(nnz_adj, TB), TB>>>(adj_rows, adj_cols, adj_vals, nnz_adj);

    // 1) XW1 = feat @ W_gc1 — fused split-3 fp16 (fp32-class)
    {
        dim3 grid(HID / 128, cdiv(NNODES, 128));
        hmma_gemm3_kernel<<<grid, 256, H_SMEM_TOTAL>>>(
            fhi, fhi, flo, whi_gc1, wlo_gc1, whi_gc1, bufA, NNODES, HID, 512, 512);
    }
    // 2) h = relu(spmm + b1) — CSR gather, split fp16 output
    spmm_gather_split_kernel<<<cdiv(NNODES, 8), TB>>>(off_enc, ecol, eval, bufA, b_gc1, hhi, hlo, NNODES);
    // 3) hW2 = h @ W_gc2 — fused split-3 fp16 (fp32-class)
    {
        dim3 grid(1, cdiv(NNODES, 128));
        hmma_gemm3_kernel<<<grid, 256, H_SMEM_TOTAL>>>(
            hhi, hhi, hlo, whi_gc2, wlo_gc2, whi_gc2, bufA, NNODES, LAT, 256, 256);
    }
    // 4) z = relu(spmm + b2)
    spmm_gather_kernel<64, false><<<cdiv(NNODES, 8), TB>>>(off_enc, ecol, eval, bufA, b_gc2, z, NNODES);
    // 5) degree + pred_deg
    degree_kernel<<<cdiv(NNODES, TB / 32), TB>>>(z, W_reg, b_reg, out_deg, pdeg, NNODES);
    // 5b) mend CSR build
    cudaMemsetAsync(cnt, 0, NODE_LEN * sizeof(int));
    mend_hist_edges_kernel<<<cdiv(E, TB), TB>>>(edges, E);
    mend_hist_new_kernel<<<cdiv(NNODES * NPRED, TB), TB>>>(pdeg);
    scan_kernel<<<1, 1024>>>(cnt, off_mend, fill, NODE_LEN);
    mend_fill_edges_kernel<<<cdiv(E, TB), TB>>>(edges, E);
    mend_fill_new_kernel<<<cdiv(NNODES * NPRED, TB), TB>>>(pdeg);
    // 6) znh = half(z + noise), zero-padded to K=128
    add_half_pad_kernel<<<cdiv((long long)NNODES * 128, TB), TB>>>(znh, z, noise);
    // 7) g1h = half(relu(znh @ W_fc1 + b)) — fp16 mma (K=128 padded)
    {
        dim3 grid(FC1N / 128, cdiv(NNODES, 128));
        hmma_gemm_kernel<1, 1><<<grid, 256, H_SMEM_TOTAL>>>(
            znh, wh_fc1, b_fc1, nullptr, g1h, NNODES, FC1N, 128, 128);
    }
    // 8) g2h = half(relu(g1h @ W_fc2 + b)) — fp16 mma
    {
        dim3 grid(FC2N / 128, cdiv(NNODES, 128));
        hmma_gemm_kernel<1, 1><<<grid, 256, H_SMEM_TOTAL>>>(
            g1h, wh_fc2, b_fc2, nullptr, g2h, NNODES, FC2N, FC1N, 256);
    }
    // 9) gen_feat = tanh(g2h @ W_flat + b) — fp16 mma 128x128 (proven config)
    {
        dim3 grid(2560 / 128, cdiv(NNODES, 128));
        hmma_gemm_kernel<2, 2><<<grid, 256, H_SMEM_TOTAL>>>(
            g2h, wh_flat, b_flat, out_gen, fillh, NNODES, GENF, FC2N, 2048);
    }
    // 10) fillW3 = fillh @ W_gc3 — fp16 mma, fp16 output
    {
        dim3 grid(HID / 128, cdiv(NODE_LEN, 128));
        hmma_gemm_kernel<0, 1><<<grid, 256, H_SMEM_TOTAL>>>(
            fillh, wh_gc3, nullptr, nullptr, fw3h, NODE_LEN, HID, 512, 512);
    }
    // 12) mend layer 1 — CSR gather (fp16 in/out), fused normalize+bias+relu
    mend_gather_h_kernel<<<cdiv(NODE_LEN, 8), TB>>>(off_mend, mcol, fw3h, b_gc3, h2h, NODE_LEN);
    // 13) c7 = h2 @ W_gc4 — skinny N=16 (fp16 input)
    skinny16_h_kernel<<<cdiv(NODE_LEN, 128), 128>>>(h2h, W_gc4, c7, NODE_LEN);
    // 14) mend layer 2 — CSR gather
    spmm_gather_kernel<16, true><<<cdiv(NODE_LEN, 8), TB>>>(off_mend, mcol, nullptr, c7, b_gc4, out_nc, NODE_LEN);

    (void)n_in; (void)out_size;
}

// round 17
// speedup vs baseline: 1.1073x; 1.0289x over previous
#include <cuda_runtime.h>
#include <cuda_fp16.h>
#include <cstdint>

// ---------------- problem constants ----------------
#define NNODES   20000
#define FEAT     500
#define HID      256
#define LAT      64
#define NPRED    5
#define NCLS     16
#define NODE_LEN (NNODES + NNODES * NPRED)      // 120000
#define GENF     (NPRED * FEAT)                 // 2500
#define FC1N     256
#define FC2N     2048

#define OUT_GEN_OFF ((long long)NNODES)
#define OUT_NC_OFF  ((long long)NNODES + (long long)NNODES * GENF)

// ---------------- scratch (static device globals; no allocation) ------------
__device__ float g_bufA[(size_t)NODE_LEN * HID];
__device__ float g_bufB[(size_t)NODE_LEN * HID];
__device__ float g_c7[(size_t)NODE_LEN * NCLS];
__device__ int   g_pdeg[NNODES];
__device__ int   g_is64;
// fp16 operands
__device__ __half g_g1h[(size_t)NNODES * FC1N];
__device__ __half g_g2h[(size_t)NNODES * FC2N];
__device__ __half g_fillh[(size_t)NODE_LEN * 512];
__device__ __half g_fhi[(size_t)NNODES * 512];
__device__ __half g_flo[(size_t)NNODES * 512];
__device__ __half g_hhi[(size_t)NNODES * 256];
__device__ __half g_hlo[(size_t)NNODES * 256];
__device__ __half g_znh[(size_t)NNODES * 128];
__device__ __half g_wh_fc2[(size_t)2048 * 256];
__device__ __half g_wh_flat[(size_t)2560 * 2048];
__device__ __half g_wh_gc3[(size_t)256 * 512];
__device__ __half g_wh_fc1[(size_t)256 * 128];
__device__ __half g_whi_gc1[(size_t)256 * 512];
__device__ __half g_wlo_gc1[(size_t)256 * 512];
__device__ __half g_whi_gc2[(size_t)128 * 256];
__device__ __half g_wlo_gc2[(size_t)128 * 256];
// CSR scratch
__device__ int   g_cnt[NODE_LEN];
__device__ int   g_fill[NODE_LEN];
__device__ int   g_off_enc[NNODES + 1];
__device__ int   g_off_mend[NODE_LEN + 1];
__device__ int   g_ecol[700000];
__device__ float g_eval[700000];
__device__ int   g_mcol[900000];

// ---------------- helpers ----------------
__device__ __forceinline__ uint32_t smem_u32(const void* p) {
    uint32_t a;
    asm("{ .reg .u64 t; cvta.to.shared.u64 t, %1; cvt.u32.u64 %0, t; }" : "=r"(a) : "l"(p));
    return a;
}
__device__ __forceinline__ void ldsm_x4(uint32_t addr, uint32_t* r) {
    asm volatile("ldmatrix.sync.aligned.m8n8.x4.shared.b16 {%0,%1,%2,%3}, [%4];"
                 : "=r"(r[0]), "=r"(r[1]), "=r"(r[2]), "=r"(r[3]) : "r"(addr));
}
__device__ __forceinline__ void mma_f16(float* c, const uint32_t* a, uint32_t b0, uint32_t b1) {
    asm volatile(
        "mma.sync.aligned.m16n8k16.row.col.f32.f16.f16.f32 "
        "{%0,%1,%2,%3}, {%4,%5,%6,%7}, {%8,%9}, {%0,%1,%2,%3};"
        : "+f"(c[0]), "+f"(c[1]), "+f"(c[2]), "+f"(c[3])
        : "r"(a[0]), "r"(a[1]), "r"(a[2]), "r"(a[3]), "r"(b0), "r"(b1));
}
#define CP_ASYNC16(dst, src) \
    asm volatile("cp.async.cg.shared.global [%0], [%1], 16;" :: "r"(dst), "l"(src))
#define CP_COMMIT() asm volatile("cp.async.commit_group;" ::: "memory")
#define CP_WAIT(n)  asm volatile("cp.async.wait_group %0;" :: "n"(n) : "memory")

// ---------------- index dtype detection ----------------
__global__ void detect_idx_kernel(const void* adj_rows) {
    int lane = threadIdx.x;
    const long long* p = (const long long*)adj_rows;
    int bad = 0;
    for (int i = lane; i < 256; i += 32) {
        long long v = p[i];
        if (v < 0 || v >= NODE_LEN) bad = 1;
    }
    unsigned m = __ballot_sync(0xffffffffu, bad);
    if (lane == 0) g_is64 = (m == 0) ? 1 : 0;
}
__device__ __forceinline__ long long load_idx(const void* p, long long i) {
    return g_is64 ? ((const long long*)p)[i] : (long long)((const int*)p)[i];
}

// ---------------- CSR build ----------------
__global__ void enc_hist_kernel(const void* __restrict__ rows, long long nnz) {
    long long e = (long long)blockIdx.x * blockDim.x + threadIdx.x;
    if (e >= nnz) return;
    atomicAdd(&g_cnt[load_idx(rows, e)], 1);
}
__global__ void enc_fill_kernel(const void* __restrict__ rows, const void* __restrict__ cols,
                                const float* __restrict__ vals, long long nnz) {
    long long e = (long long)blockIdx.x * blockDim.x + threadIdx.x;
    if (e >= nnz) return;
    int r = (int)load_idx(rows, e);
    int pos = atomicAdd(&g_fill[r], 1);
    g_ecol[pos] = (int)load_idx(cols, e);
    g_eval[pos] = vals[e];
}
__global__ void scan_kernel(const int* __restrict__ cnt, int* __restrict__ off,
                            int* __restrict__ fill, int n) {
    __shared__ int part[1024];
    int t = threadIdx.x;
    int chunk = (n + 1023) >> 10;
    int lo = t * chunk, hi = lo + chunk;
    if (hi > n) hi = n;
    int s = 0;
    for (int i = lo; i < hi; i++) s += cnt[i];
    part[t] = s;
    __syncthreads();
    for (int d = 1; d < 1024; d <<= 1) {
        int add = (t >= d) ? part[t - d] : 0;
        __syncthreads();
        part[t] += add;
        __syncthreads();
    }
    int run = part[t] - s;
    for (int i = lo; i < hi; i++) {
        off[i] = run; fill[i] = run;
        run += cnt[i];
    }
    if (t == 1023) off[n] = part[1023];
}
__global__ void mend_hist_edges_kernel(const void* __restrict__ edges, int E) {
    int e = blockIdx.x * blockDim.x + threadIdx.x;
    if (e >= E) return;
    int lo = (int)load_idx(edges, 2LL * e);
    int hi = (int)load_idx(edges, 2LL * e + 1);
    atomicAdd(&g_cnt[lo], 1);
    atomicAdd(&g_cnt[hi], 1);
}
__global__ void mend_hist_new_kernel(const int* __restrict__ pdeg) {
    int t = blockIdx.x * blockDim.x + threadIdx.x;
    if (t >= NNODES * NPRED) return;
    int node = t / NPRED, j = t - node * NPRED;
    if (j < pdeg[node]) {
        atomicAdd(&g_cnt[node], 1);
        g_cnt[NNODES + t] = 1;
    }
}
__global__ void mend_fill_edges_kernel(const void* __restrict__ edges, int E) {
    int e = blockIdx.x * blockDim.x + threadIdx.x;
    if (e >= E) return;
    int lo = (int)load_idx(edges, 2LL * e);
    int hi = (int)load_idx(edges, 2LL * e + 1);
    int p0 = atomicAdd(&g_fill[lo], 1);
    g_mcol[p0] = hi;
    int p1 = atomicAdd(&g_fill[hi], 1);
    g_mcol[p1] = lo;
}
__global__ void mend_fill_new_kernel(const int* __restrict__ pdeg) {
    int t = blockIdx.x * blockDim.x + threadIdx.x;
    if (t >= NNODES * NPRED) return;
    int node = t / NPRED, j = t - node * NPRED;
    if (j < pdeg[node]) {
        int p0 = atomicAdd(&g_fill[node], 1);
        g_mcol[p0] = NNODES + t;
        g_mcol[g_off_mend[NNODES + t]] = node;
    }
}

// ---------------- gather SpMM (warp per row) ----------------
template <int D, bool MEND>
__global__ void spmm_gather_kernel(const int* __restrict__ off, const int* __restrict__ cols,
                                   const float* __restrict__ vals,
                                   const float* __restrict__ x, const float* __restrict__ bias,
                                   float* __restrict__ y, int nrows)
{
    int w = (int)(((long long)blockIdx.x * blockDim.x + threadIdx.x) >> 5);
    int lane = threadIdx.x & 31;
    if (w >= nrows) return;
    int e0 = off[w], e1 = off[w + 1];

    if (D == 256) {
        float a[8] = {0, 0, 0, 0, 0, 0, 0, 0};
        const int cb = lane * 4;
        for (int e = e0; e < e1; e++) {
            long long c = cols[e];
            float4 t0 = *(const float4*)(x + c * 256 + cb);
            float4 t1 = *(const float4*)(x + c * 256 + 128 + cb);
            a[0] += t0.x; a[1] += t0.y; a[2] += t0.z; a[3] += t0.w;
            a[4] += t1.x; a[5] += t1.y; a[6] += t1.z; a[7] += t1.w;
        }
        float4 o0, o1;
        float inv = 1.0f / (1.0f + (float)(e1 - e0));
        const float* xr = x + (long long)w * 256;
        o0.x = fmaxf((a[0] + xr[cb + 0]) * inv + bias[cb + 0], 0.f);
        o0.y = fmaxf((a[1] + xr[cb + 1]) * inv + bias[cb + 1], 0.f);
        o0.z = fmaxf((a[2] + xr[cb + 2]) * inv + bias[cb + 2], 0.f);
        o0.w = fmaxf((a[3] + xr[cb + 3]) * inv + bias[cb + 3], 0.f);
        o1.x = fmaxf((a[4] + xr[128 + cb + 0]) * inv + bias[128 + cb + 0], 0.f);
        o1.y = fmaxf((a[5] + xr[128 + cb + 1]) * inv + bias[128 + cb + 1], 0.f);
        o1.z = fmaxf((a[6] + xr[128 + cb + 2]) * inv + bias[128 + cb + 2], 0.f);
        o1.w = fmaxf((a[7] + xr[128 + cb + 3]) * inv + bias[128 + cb + 3], 0.f);
        *(float4*)(y + (long long)w * 256 + cb) = o0;
        *(float4*)(y + (long long)w * 256 + 128 + cb) = o1;
    } else {  // D == 16, MEND
        if (lane < 16) {
            float a = 0.f;
            for (int e = e0; e < e1; e++)
                a += x[(long long)cols[e] * 16 + lane];
            float inv = 1.0f / (1.0f + (float)(e1 - e0));
            float v = (a + x[(long long)w * 16 + lane]) * inv + bias[lane];
            y[(long long)w * 16 + lane] = fmaxf(v, 0.f);
        }
    }
}

// fused step 4+5+6: z-gather (D=64) + degree regressor + znh = half(z+noise) padded
__global__ void spmm_gather_z_kernel(const int* __restrict__ off, const int* __restrict__ cols,
                                     const float* __restrict__ vals,
                                     const float* __restrict__ x, const float* __restrict__ bias,
                                     const float* __restrict__ Wr, const float* __restrict__ br,
                                     const float* __restrict__ noise,
                                     float* __restrict__ deg_out, int* __restrict__ pdeg,
                                     __half* __restrict__ znh, int nrows)
{
    int w = (int)(((long long)blockIdx.x * blockDim.x + threadIdx.x) >> 5);
    int lane = threadIdx.x & 31;
    if (w >= nrows) return;
    int e0 = off[w], e1 = off[w + 1];

    float a0 = 0.f, a1 = 0.f;
    const int cb = lane * 2;
    for (int e = e0; e < e1; e++) {
        long long c = cols[e];
        float2 t = *(const float2*)(x + c * 64 + cb);
        float v = vals[e];
        a0 += v * t.x; a1 += v * t.y;
    }
    float z0 = fmaxf(a0 + bias[cb + 0], 0.f);
    float z1 = fmaxf(a1 + bias[cb + 1], 0.f);
    // degree = relu(z . W_reg + b_reg)
    float s = z0 * Wr[cb + 0] + z1 * Wr[cb + 1];
#pragma unroll
    for (int o = 16; o; o >>= 1) s += __shfl_xor_sync(0xffffffffu, s, o);
    if (lane == 0) {
        float d = fmaxf(s + br[0], 0.0f);
        deg_out[w] = d;
        int pi = (int)d;
        if (pi > NPRED) pi = NPRED;
        pdeg[w] = pi;
    }
    // znh row (padded to 128)
    float2 nz = *(const float2*)(noise + (long long)w * 64 + cb);
    __half2* py = (__half2*)(znh + (long long)w * 128);
    py[lane] = __floats2half2_rn(z0 + nz.x, z1 + nz.y);
    py[32 + lane] = __halves2half2(__half(0.0f), __half(0.0f));
}

// encoder gather D=256 writing split fp16 (hi, lo)
__global__ void spmm_gather_split_kernel(const int* __restrict__ off, const int* __restrict__ cols,
                                         const float* __restrict__ vals,
                                         const float* __restrict__ x, const float* __restrict__ bias,
                                         __half* __restrict__ yhi, __half* __restrict__ ylo, int nrows)
{
    int w = (int)(((long long)blockIdx.x * blockDim.x + threadIdx.x) >> 5);
    int lane = threadIdx.x & 31;
    if (w >= nrows) return;
    int e0 = off[w], e1 = off[w + 1];
    float a[8] = {0, 0, 0, 0, 0, 0, 0, 0};
    const int cb = lane * 4;
    for (int e = e0; e < e1; e++) {
        long long c = cols[e];
        float4 t0 = *(const float4*)(x + c * 256 + cb);
        float4 t1 = *(const float4*)(x + c * 256 + 128 + cb);
        float v = vals[e];
        a[0] += v * t0.x; a[1] += v * t0.y; a[2] += v * t0.z; a[3] += v * t0.w;
        a[4] += v * t1.x; a[5] += v * t1.y; a[6] += v * t1.z; a[7] += v * t1.w;
    }
#pragma unroll
    for (int g = 0; g < 2; g++) {
        int base = g * 128 + cb;
        float v0 = fmaxf(a[4 * g + 0] + bias[base + 0], 0.f);
        float v1 = fmaxf(a[4 * g + 1] + bias[base + 1], 0.f);
        float v2 = fmaxf(a[4 * g + 2] + bias[base + 2], 0.f);
        float v3 = fmaxf(a[4 * g + 3] + bias[base + 3], 0.f);
        __half h0 = __float2half_rn(v0), h1 = __float2half_rn(v1);
        __half h2 = __float2half_rn(v2), h3 = __float2half_rn(v3);
        long long o = (long long)w * 256 + base;
        *(__half2*)(yhi + o)     = __halves2half2(h0, h1);
        *(__half2*)(yhi + o + 2) = __halves2half2(h2, h3);
        *(__half2*)(ylo + o)     = __halves2half2(__float2half_rn(v0 - __half2float(h0)),
                                                  __float2half_rn(v1 - __half2float(h1)));
        *(__half2*)(ylo + o + 2) = __halves2half2(__float2half_rn(v2 - __half2float(h2)),
                                                  __float2half_rn(v3 - __half2float(h3)));
    }
}

// ---------------- weight transpose -> half ----------------
__global__ void transpose_half_kernel(const float* __restrict__ W, __half* __restrict__ WT,
                                      int K, int N, int Kpad, int Npad) {
    __shared__ float tile[32][33];
    int kb = blockIdx.x * 32, nb = blockIdx.y * 32;
    int tx = threadIdx.x, ty = threadIdx.y;   // 32 x 8
#pragma unroll
    for (int i = 0; i < 4; i++) {
        int k = kb + ty + i * 8, n = nb + tx;
        tile[ty + i * 8][tx] = (k < K && n < N) ? W[(long long)k * N + n] : 0.0f;
    }
    __syncthreads();
#pragma unroll
    for (int i = 0; i < 4; i++) {
        int n = nb + ty + i * 8, k = kb + tx;
        if (n < Npad && k < Kpad)
            WT[(long long)n * Kpad + k] = __float2half_rn(tile[tx][ty + i * 8]);
    }
}
__global__ void transpose_half_split_kernel(const float* __restrict__ W,
                                            __half* __restrict__ WThi, __half* __restrict__ WTlo,
                                            int K, int N, int Kpad, int Npad) {
    __shared__ float tile[32][33];
    int kb = blockIdx.x * 32, nb = blockIdx.y * 32;
    int tx = threadIdx.x, ty = threadIdx.y;
#pragma unroll
    for (int i = 0; i < 4; i++) {
        int k = kb + ty + i * 8, n = nb + tx;
        tile[ty + i * 8][tx] = (k < K && n < N) ? W[(long long)k * N + n] : 0.0f;
    }
    __syncthreads();
#pragma unroll
    for (int i = 0; i < 4; i++) {
        int n = nb + ty + i * 8, k = kb + tx;
        if (n < Npad && k < Kpad) {
            float v = tile[tx][ty + i * 8];
            __half h = __float2half_rn(v);
            WThi[(long long)n * Kpad + k] = h;
            WTlo[(long long)n * Kpad + k] = __float2half_rn(v - __half2float(h));
        }
    }
}
__global__ void feat_prep_kernel(const float* __restrict__ feat,
                                 __half* __restrict__ fhi, __half* __restrict__ flo,
                                 __half* __restrict__ fillh) {
    long long i = (long long)blockIdx.x * blockDim.x + threadIdx.x;
    if (i >= (long long)NNODES * 512) return;
    int r = (int)(i >> 9), c = (int)(i & 511);
    float v = (c < FEAT) ? feat[(long long)r * FEAT + c] : 0.0f;
    __half h = __float2half_rn(v);
    fhi[i] = h;
    flo[i] = __float2half_rn(v - __half2float(h));
    fillh[i] = h;
}

// ---------------- fp16 mma GEMM (128x128) ------------------
#define HSTAGES 4
#define H_STRIDE_B 80
#define H_MAT_BYTES (128 * H_STRIDE_B)          // 10240
#define H_STAGE_BYTES (2 * H_MAT_BYTES)         // 20480
#define H_SMEM_TOTAL (HSTAGES * H_STAGE_BYTES)  // 81920

// EPI: 0 none, 1 bias+relu, 2 bias+tanh.  OUT: 0 f32 C, 1 half Ch, 2 f32 C + genh->fillh
template <int EPI, int OUT>
__global__ void __launch_bounds__(256, 2) hmma_gemm_kernel(
    const __half* __restrict__ A, const __half* __restrict__ BT,
    const float* __restrict__ bias,
    float* __restrict__ C, __half* __restrict__ Ch,
    int M, int N, int K, int Kpad)
{
    extern __shared__ char smem[];
    const uint32_t sbase = smem_u32(smem);
    const int tid = threadIdx.x;
    const int wid = tid >> 5, lane = tid & 31;
    const int gid = lane >> 2, tig = lane & 3;
    const int warp_m = wid & 3, warp_n = wid >> 2;
    const int m0 = blockIdx.y * 128, n0 = blockIdx.x * 128;

    const int crow = tid >> 1;
    const int cboff = (tid & 1) * 32;

    const __half* aptr;
    {
        int r = m0 + crow;
        int rr = (r < M) ? r : (M - 1);
        aptr = A + (long long)rr * K;
    }
    const __half* bptr = BT + (long long)(n0 + crow) * Kpad;

    const uint32_t sA_wr = sbase + (uint32_t)crow * H_STRIDE_B + (uint32_t)cboff;
    const uint32_t sB_wr = sA_wr + H_MAT_BYTES;

    const int nChunks = K >> 5;

    auto issue = [&](int chunk) {
        int s = chunk & (HSTAGES - 1);
        uint32_t da = sA_wr + (uint32_t)s * H_STAGE_BYTES;
        uint32_t db = sB_wr + (uint32_t)s * H_STAGE_BYTES;
        const char* ga = (const char*)aptr + chunk * 64 + cboff;
        const char* gb = (const char*)bptr + chunk * 64 + cboff;
        CP_ASYNC16(da, ga); CP_ASYNC16(da + 16, ga + 16);
        CP_ASYNC16(db, gb); CP_ASYNC16(db + 16, gb + 16);
        CP_COMMIT();
    };

    float acc[2][8][4];
#pragma unroll
    for (int f = 0; f < 2; f++)
#pragma unroll
        for (int j = 0; j < 8; j++)
#pragma unroll
            for (int q = 0; q < 4; q++) acc[f][j][q] = 0.0f;

    for (int s = 0; s < HSTAGES - 1; s++) issue(s);

    uint32_t a_off[2];
#pragma unroll
    for (int f = 0; f < 2; f++) {
        uint32_t row = (uint32_t)(warp_m * 32 + f * 16 + (lane & 15));
        uint32_t colb = (uint32_t)((lane >> 4) << 4);
        a_off[f] = row * H_STRIDE_B + colb;
    }
    uint32_t b_off[4];
#pragma unroll
    for (int jp = 0; jp < 4; jp++) {
        uint32_t row = (uint32_t)(warp_n * 64 + jp * 16 + ((lane >> 4) << 3) + (lane & 7));
        uint32_t colb = (uint32_t)(((lane >> 3) & 1) << 4);
        b_off[jp] = row * H_STRIDE_B + colb;
    }

    CP_WAIT(HSTAGES - 2);
    __syncthreads();

    for (int i = 0; i < nChunks; i++) {
        uint32_t sA = sbase + (uint32_t)(i & (HSTAGES - 1)) * H_STAGE_BYTES;
        uint32_t sB = sA + H_MAT_BYTES;
#pragma unroll
        for (int kk = 0; kk < 2; kk++) {
            uint32_t afr[2][4];
            ldsm_x4(sA + a_off[0] + kk * 32, afr[0]);
            ldsm_x4(sA + a_off[1] + kk * 32, afr[1]);
#pragma unroll
            for (int jp = 0; jp < 4; jp++) {
                uint32_t br[4];
                ldsm_x4(sB + b_off[jp] + kk * 32, br);
                mma_f16(acc[0][2 * jp + 0], afr[0], br[0], br[1]);
                mma_f16(acc[1][2 * jp + 0], afr[1], br[0], br[1]);
                mma_f16(acc[0][2 * jp + 1], afr[0], br[2], br[3]);
                mma_f16(acc[1][2 * jp + 1], afr[1], br[2], br[3]);
            }
        }
        if (i + HSTAGES - 1 < nChunks) issue(i + HSTAGES - 1);
        else CP_COMMIT();
        CP_WAIT(HSTAGES - 2);
        __syncthreads();
    }

#pragma unroll
    for (int f = 0; f < 2; f++) {
#pragma unroll
        for (int rr = 0; rr < 2; rr++) {
            int r = m0 + warp_m * 32 + f * 16 + rr * 8 + gid;
            if (r >= M) continue;
#pragma unroll
            for (int j = 0; j < 8; j++) {
                int c = n0 + warp_n * 64 + j * 8 + tig * 2;
                if (c >= N) continue;
                float v0 = acc[f][j][rr * 2 + 0], v1 = acc[f][j][rr * 2 + 1];
                if (EPI >= 1) { v0 += bias[c]; v1 += bias[c + 1]; }
                if (EPI == 1) { v0 = fmaxf(v0, 0.f); v1 = fmaxf(v1, 0.f); }
                if (EPI == 2) { v0 = tanhf(v0); v1 = tanhf(v1); }
                if (OUT == 0) {
                    *(float2*)(C + (long long)r * N + c) = make_float2(v0, v1);
                } else if (OUT == 1) {
                    *(__half2*)(Ch + (long long)r * N + c) = __floats2half2_rn(v0, v1);
                } else {
                    *(float2*)(C + (long long)r * N + c) = make_float2(v0, v1);
                    int j5 = c / FEAT, cc = c - j5 * FEAT;
                    *(__half2*)(Ch + ((size_t)(NNODES + r * NPRED + j5) * 512 + cc)) =
                        __floats2half2_rn(v0, v1);
                }
            }
        }
    }
}

// ---------------- triple-pass split-3 GEMM: C = A0@B0 + A1@B1 + A2@B2 ------
__global__ void __launch_bounds__(256, 2) hmma_gemm3_kernel(
    const __half* __restrict__ A0, const __half* __restrict__ A1, const __half* __restrict__ A2,
    const __half* __restrict__ B0, const __half* __restrict__ B1, const __half* __restrict__ B2,
    float* __restrict__ C, int M, int N, int K, int Kpad)
{
    extern __shared__ char smem[];
    const uint32_t sbase = smem_u32(smem);
    const int tid = threadIdx.x;
    const int wid = tid >> 5, lane = tid & 31;
    const int gid = lane >> 2, tig = lane & 3;
    const int warp_m = wid & 3, warp_n = wid >> 2;
    const int m0 = blockIdx.y * 128, n0 = blockIdx.x * 128;

    const int crow = tid >> 1;
    const int cboff = (tid & 1) * 32;

    int rr = (m0 + crow < M) ? (m0 + crow) : (M - 1);
    const __half* ap0 = A0 + (long long)rr * K;
    const __half* ap1 = A1 + (long long)rr * K;
    const __half* ap2 = A2 + (long long)rr * K;
    const __half* bp0 = B0 + (long long)(n0 + crow) * Kpad;
    const __half* bp1 = B1 + (long long)(n0 + crow) * Kpad;
    const __half* bp2 = B2 + (long long)(n0 + crow) * Kpad;

    const uint32_t sA_wr = sbase + (uint32_t)crow * H_STRIDE_B + (uint32_t)cboff;
    const uint32_t sB_wr = sA_wr + H_MAT_BYTES;

    const int nChunks = K >> 5;
    const int total = 3 * nChunks;

    auto issue = [&](int t) {
        int pass = t / nChunks;
        int local = t - pass * nChunks;
        const __half* ga = (pass == 0) ? ap0 : (pass == 1) ? ap1 : ap2;
        const __half* gb = (pass == 0) ? bp0 : (pass == 1) ? bp1 : bp2;
        int s = t & (HSTAGES - 1);
        uint32_t da = sA_wr + (uint32_t)s * H_STAGE_BYTES;
        uint32_t db = sB_wr + (uint32_t)s * H_STAGE_BYTES;
        const char* pa = (const char*)ga + local * 64 + cboff;
        const char* pb = (const char*)gb + local * 64 + cboff;
        CP_ASYNC16(da, pa); CP_ASYNC16(da + 16, pa + 16);
        CP_ASYNC16(db, pb); CP_ASYNC16(db + 16, pb + 16);
        CP_COMMIT();
    };

    float acc[2][8][4];
#pragma unroll
    for (int f = 0; f < 2; f++)
#pragma unroll
        for (int j = 0; j < 8; j++)
#pragma unroll
            for (int q = 0; q < 4; q++) acc[f][j][q] = 0.0f;

    for (int s = 0; s < HSTAGES - 1; s++) issue(s);

    uint32_t a_off[2];
#pragma unroll
    for (int f = 0; f < 2; f++) {
        uint32_t row = (uint32_t)(warp_m * 32 + f * 16 + (lane & 15));
        uint32_t colb = (uint32_t)((lane >> 4) << 4);
        a_off[f] = row * H_STRIDE_B + colb;
    }
    uint32_t b_off[4];
#pragma unroll
    for (int jp = 0; jp < 4; jp++) {
        uint32_t row = (uint32_t)(warp_n * 64 + jp * 16 + ((lane >> 4) << 3) + (lane & 7));
        uint32_t colb = (uint32_t)(((lane >> 3) & 1) << 4);
        b_off[jp] = row * H_STRIDE_B + colb;
    }

    CP_WAIT(HSTAGES - 2);
    __syncthreads();

    for (int i = 0; i < total; i++) {
        uint32_t sA = sbase + (uint32_t)(i & (HSTAGES - 1)) * H_STAGE_BYTES;
        uint32_t sB = sA + H_MAT_BYTES;
#pragma unroll
        for (int kk = 0; kk < 2; kk++) {
            uint32_t afr[2][4];
            ldsm_x4(sA + a_off[0] + kk * 32, afr[0]);
            ldsm_x4(sA + a_off[1] + kk * 32, afr[1]);
#pragma unroll
            for (int jp = 0; jp < 4; jp++) {
                uint32_t br[4];
                ldsm_x4(sB + b_off[jp] + kk * 32, br);
                mma_f16(acc[0][2 * jp + 0], afr[0], br[0], br[1]);
                mma_f16(acc[1][2 * jp + 0], afr[1], br[0], br[1]);
                mma_f16(acc[0][2 * jp + 1], afr[0], br[2], br[3]);
                mma_f16(acc[1][2 * jp + 1], afr[1], br[2], br[3]);
            }
        }
        if (i + HSTAGES - 1 < total) issue(i + HSTAGES - 1);
        else CP_COMMIT();
        CP_WAIT(HSTAGES - 2);
        __syncthreads();
    }

#pragma unroll
    for (int f = 0; f < 2; f++) {
#pragma unroll
        for (int rr2 = 0; rr2 < 2; rr2++) {
            int r = m0 + warp_m * 32 + f * 16 + rr2 * 8 + gid;
            if (r >= M) continue;
#pragma unroll
            for (int j = 0; j < 8; j++) {
                int c = n0 + warp_n * 64 + j * 8 + tig * 2;
                if (c >= N) continue;
                *(float2*)(C + (long long)r * N + c) =
                    make_float2(acc[f][j][rr2 * 2 + 0], acc[f][j][rr2 * 2 + 1]);
            }
        }
    }
}

// ---------------- skinny GEMM for gc4 ----------------
__global__ void skinny16_kernel(const float* __restrict__ X, const float* __restrict__ W,
                                float* __restrict__ C, int M)
{
    __shared__ float Ws[256 * 16];
    int tid = threadIdx.x;   // 128
    for (int i = tid; i < 256 * 16; i += 128) Ws[i] = W[i];
    __syncthreads();
    int r = blockIdx.x * 128 + tid;
    if (r >= M) return;
    const float* x = X + (long long)r * 256;
    float acc[16];
#pragma unroll
    for (int q = 0; q < 16; q++) acc[q] = 0.0f;
    for (int k = 0; k < 256; k += 4) {
        float4 a = *(const float4*)(x + k);
#pragma unroll
        for (int q = 0; q < 16; q++)
            acc[q] += a.x * Ws[(k + 0) * 16 + q] + a.y * Ws[(k + 1) * 16 + q]
                    + a.z * Ws[(k + 2) * 16 + q] + a.w * Ws[(k + 3) * 16 + q];
    }
    float* co = C + (long long)r * 16;
#pragma unroll
    for (int q = 0; q < 16; q += 4)
        *(float4*)(co + q) = make_float4(acc[q], acc[q + 1], acc[q + 2], acc[q + 3]);
}

// ---------------- host ----------------
static inline int cdiv(long long a, long long b) { return (int)((a + b - 1) / b); }

extern "C" void kernel_launch(void* const* d_in, const int* in_sizes, int n_in,
                              void* d_out, int out_size)
{
    const float* feat     = (const float*)d_in[0];
    const void*  edges    = d_in[1];
    const void*  adj_rows = d_in[2];
    const void*  adj_cols = d_in[3];
    const float* adj_vals = (const float*)d_in[4];
    const float* noise    = (const float*)d_in[5];
    const float* W_gc1 = (const float*)d_in[6];   const float* b_gc1 = (const float*)d_in[7];
    const float* W_gc2 = (const float*)d_in[8];   const float* b_gc2 = (const float*)d_in[9];
    const float* W_reg = (const float*)d_in[10];  const float* b_reg = (const float*)d_in[11];
    const float* W_fc1 = (const float*)d_in[12];  const float* b_fc1 = (const float*)d_in[13];
    const float* W_fc2 = (const float*)d_in[14];  const float* b_fc2 = (const float*)d_in[15];
    const float* W_flat = (const float*)d_in[16]; const float* b_flat = (const float*)d_in[17];
    const float* W_gc3 = (const float*)d_in[18];  const float* b_gc3 = (const float*)d_in[19];
    const float* W_gc4 = (const float*)d_in[20];  const float* b_gc4 = (const float*)d_in[21];

    float* out = (float*)d_out;
    float* out_deg = out;
    float* out_gen = out + OUT_GEN_OFF;
    float* out_nc  = out + OUT_NC_OFF;

    const long long nnz_adj = in_sizes[2];
    const int E = in_sizes[1] / 2;

    void* p;
    float *bufA, *bufB, *c7;
    __half *g1h, *g2h, *fillh, *fhi, *flo, *hhi, *hlo, *znh;
    __half *wh_fc2, *wh_flat, *wh_gc3, *wh_fc1, *whi_gc1, *wlo_gc1, *whi_gc2, *wlo_gc2;
    int *pdeg, *cnt, *fill, *off_enc, *off_mend, *ecol, *mcol;
    float *eval;
    cudaGetSymbolAddress(&p, g_bufA);  bufA  = (float*)p;
    cudaGetSymbolAddress(&p, g_bufB);  bufB  = (float*)p;
    cudaGetSymbolAddress(&p, g_c7);    c7    = (float*)p;
    cudaGetSymbolAddress(&p, g_pdeg);  pdeg  = (int*)p;
    cudaGetSymbolAddress(&p, g_cnt);   cnt   = (int*)p;
    cudaGetSymbolAddress(&p, g_fill);  fill  = (int*)p;
    cudaGetSymbolAddress(&p, g_off_enc);  off_enc  = (int*)p;
    cudaGetSymbolAddress(&p, g_off_mend); off_mend = (int*)p;
    cudaGetSymbolAddress(&p, g_ecol);  ecol  = (int*)p;
    cudaGetSymbolAddress(&p, g_eval);  eval  = (float*)p;
    cudaGetSymbolAddress(&p, g_mcol);  mcol  = (int*)p;
    cudaGetSymbolAddress(&p, g_g1h);   g1h   = (__half*)p;
    cudaGetSymbolAddress(&p, g_g2h);   g2h   = (__half*)p;
    cudaGetSymbolAddress(&p, g_fillh); fillh = (__half*)p;
    cudaGetSymbolAddress(&p, g_fhi);   fhi   = (__half*)p;
    cudaGetSymbolAddress(&p, g_flo);   flo   = (__half*)p;
    cudaGetSymbolAddress(&p, g_hhi);   hhi   = (__half*)p;
    cudaGetSymbolAddress(&p, g_hlo);   hlo   = (__half*)p;
    cudaGetSymbolAddress(&p, g_znh);   znh   = (__half*)p;
    cudaGetSymbolAddress(&p, g_wh_fc2);  wh_fc2  = (__half*)p;
    cudaGetSymbolAddress(&p, g_wh_flat); wh_flat = (__half*)p;
    cudaGetSymbolAddress(&p, g_wh_gc3);  wh_gc3  = (__half*)p;
    cudaGetSymbolAddress(&p, g_wh_fc1);  wh_fc1  = (__half*)p;
    cudaGetSymbolAddress(&p, g_whi_gc1); whi_gc1 = (__half*)p;
    cudaGetSymbolAddress(&p, g_wlo_gc1); wlo_gc1 = (__half*)p;
    cudaGetSymbolAddress(&p, g_whi_gc2); whi_gc2 = (__half*)p;
    cudaGetSymbolAddress(&p, g_wlo_gc2); wlo_gc2 = (__half*)p;

    cudaFuncSetAttribute((const void*)hmma_gemm_kernel<0, 0>,
                         cudaFuncAttributeMaxDynamicSharedMemorySize, H_SMEM_TOTAL);
    cudaFuncSetAttribute((const void*)hmma_gemm_kernel<1, 1>,
                         cudaFuncAttributeMaxDynamicSharedMemorySize, H_SMEM_TOTAL);
    cudaFuncSetAttribute((const void*)hmma_gemm_kernel<2, 2>,
                         cudaFuncAttributeMaxDynamicSharedMemorySize, H_SMEM_TOTAL);
    cudaFuncSetAttribute((const void*)hmma_gemm3_kernel,
                         cudaFuncAttributeMaxDynamicSharedMemorySize, H_SMEM_TOTAL);

    const int TB = 256;
    dim3 tblk(32, 8);

    // 0) prep
    detect_idx_kernel<<<1, 32>>>(adj_rows);
    transpose_half_kernel<<<dim3(cdiv(256, 32), cdiv(2048, 32)), tblk>>>(W_fc2, wh_fc2, 256, 2048, 256, 2048);
    transpose_half_kernel<<<dim3(cdiv(2048, 32), cdiv(2560, 32)), tblk>>>(W_flat, wh_flat, 2048, 2500, 2048, 2560);
    transpose_half_kernel<<<dim3(cdiv(512, 32), cdiv(256, 32)), tblk>>>(W_gc3, wh_gc3, 500, 256, 512, 256);
    transpose_half_kernel<<<dim3(cdiv(128, 32), cdiv(256, 32)), tblk>>>(W_fc1, wh_fc1, 64, 256, 128, 256);
    transpose_half_split_kernel<<<dim3(cdiv(512, 32), cdiv(256, 32)), tblk>>>(W_gc1, whi_gc1, wlo_gc1, 500, 256, 512, 256);
    transpose_half_split_kernel<<<dim3(cdiv(256, 32), cdiv(128, 32)), tblk>>>(W_gc2, whi_gc2, wlo_gc2, 256, 64, 256, 128);
    feat_prep_kernel<<<cdiv((long long)NNODES * 512, TB), TB>>>(feat, fhi, flo, fillh);

    // 0b) encoder CSR build
    cudaMemsetAsync(cnt, 0, NNODES * sizeof(int));
    enc_hist_kernel<<<cdiv(nnz_adj, TB), TB>>>(adj_rows, nnz_adj);
    scan_kernel<<<1, 1024>>>(cnt, off_enc, fill, NNODES);
    enc_fill_kernel<<<cdiv(nnz_adj, TB), TB>>>(adj_rows, adj_cols, adj_vals, nnz_adj);

    // 1) XW1 = feat @ W_gc1 — fused split-3 fp16 (fp32-class)
    {
        dim3 grid(HID / 128, cdiv(NNODES, 128));
        hmma_gemm3_kernel<<<grid, 256, H_SMEM_TOTAL>>>(
            fhi, fhi, flo, whi_gc1, wlo_gc1, whi_gc1, bufA, NNODES, HID, 512, 512);
    }
    // 2) h = relu(spmm + b1) — CSR gather, split fp16 output
    spmm_gather_split_kernel<<<cdiv(NNODES, 8), TB>>>(off_enc, ecol, eval, bufA, b_gc1, hhi, hlo, NNODES);
    // 3) hW2 = h @ W_gc2 — fused split-3 fp16 (fp32-class)
    {
        dim3 grid(1, cdiv(NNODES, 128));
        hmma_gemm3_kernel<<<grid, 256, H_SMEM_TOTAL>>>(
            hhi, hhi, hlo, whi_gc2, wlo_gc2, whi_gc2, bufA, NNODES, LAT, 256, 256);
    }
    // 4+5+6) fused: z-gather + degree + znh
    spmm_gather_z_kernel<<<cdiv(NNODES, 8), TB>>>(off_enc, ecol, eval, bufA, b_gc2,
                                                  W_reg, b_reg, noise, out_deg, pdeg, znh, NNODES);
    // 5b) mend CSR build
    cudaMemsetAsync(cnt, 0, NODE_LEN * sizeof(int));
    mend_hist_edges_kernel<<<cdiv(E, TB), TB>>>(edges, E);
    mend_hist_new_kernel<<<cdiv(NNODES * NPRED, TB), TB>>>(pdeg);
    scan_kernel<<<1, 1024>>>(cnt, off_mend, fill, NODE_LEN);
    mend_fill_edges_kernel<<<cdiv(E, TB), TB>>>(edges, E);
    mend_fill_new_kernel<<<cdiv(NNODES * NPRED, TB), TB>>>(pdeg);
    // 7) g1h = half(relu(znh @ W_fc1 + b)) — fp16 mma (K=128 padded)
    {
        dim3 grid(FC1N / 128, cdiv(NNODES, 128));
        hmma_gemm_kernel<1, 1><<<grid, 256, H_SMEM_TOTAL>>>(
            znh, wh_fc1, b_fc1, nullptr, g1h, NNODES, FC1N, 128, 128);
    }
    // 8) g2h = half(relu(g1h @ W_fc2 + b)) — fp16 mma
    {
        dim3 grid(FC2N / 128, cdiv(NNODES, 128));
        hmma_gemm_kernel<1, 1><<<grid, 256, H_SMEM_TOTAL>>>(
            g1h, wh_fc2, b_fc2, nullptr, g2h, NNODES, FC2N, FC1N, 256);
    }
    // 9) gen_feat = tanh(g2h @ W_flat + b) — fp16 mma 128x128 (proven config)
    {
        dim3 grid(2560 / 128, cdiv(NNODES, 128));
        hmma_gemm_kernel<2, 2><<<grid, 256, H_SMEM_TOTAL>>>(
            g2h, wh_flat, b_flat, out_gen, fillh, NNODES, GENF, FC2N, 2048);
    }
    // 10) fillW3 = fillh @ W_gc3 — fp16 mma, f32 output (proven R13 config)
    {
        dim3 grid(HID / 128, cdiv(NODE_LEN, 128));
        hmma_gemm_kernel<0, 0><<<grid, 256, H_SMEM_TOTAL>>>(
            fillh, wh_gc3, nullptr, bufA, nullptr, NODE_LEN, HID, 512, 512);
    }
    // 12) mend layer 1 — CSR gather (f32), fused normalize+bias+relu
    spmm_gather_kernel<256, true><<<cdiv(NODE_LEN, 8), TB>>>(off_mend, mcol, nullptr, bufA, b_gc3, bufB, NODE_LEN);
    // 13) c7 = h2 @ W_gc4 — skinny N=16 (f32)
    skinny16_kernel<<<cdiv(NODE_LEN, 128), 128>>>(bufB, W_gc4, c7, NODE_LEN);
    // 14) mend layer 2 — CSR gather
    spmm_gather_kernel<16, true><<<cdiv(NODE_LEN, 8), TB>>>(off_mend, mcol, nullptr, c7, b_gc4, out_nc, NODE_LEN);

    (void)n_in; (void)out_size;
}